// round 3
// baseline (speedup 1.0000x reference)
#include <cuda_runtime.h>
#include <math_constants.h>
#include <cstdint>

#define Bv 2
#define Tv 2048
#define Dv 1024
#define Hv 16
#define DHv 64
constexpr int MROWS = Bv * Tv;          // 4096
constexpr int NWORDS = Bv * Tv * (Tv / 32);  // 262144 packed mask words

// Scratch (allocation-free rule: __device__ globals)
__device__ float g_xn[MROWS * Dv];
__device__ float g_q[MROWS * Dv];
__device__ float g_k[MROWS * Dv];
__device__ float g_v[MROWS * Dv];
__device__ float g_y[MROWS * Dv];
__device__ unsigned g_mbits[NWORDS];

// ---------------------------------------------------------------------------
// Pack src_mask (int32 0/1, [B,T,T]) into bitmask words: bit set = attend.
// One warp produces one 32-bit word via ballot. Coalesced reads.
// ---------------------------------------------------------------------------
__global__ void __launch_bounds__(256) pack_mask_kernel(const int* __restrict__ mask,
                                                        unsigned* __restrict__ bits)
{
    int w = blockIdx.x * (blockDim.x >> 5) + (threadIdx.x >> 5);
    int lane = threadIdx.x & 31;
    int v = mask[(size_t)w * 32 + lane];
    unsigned b = __ballot_sync(0xffffffffu, v != 0);
    if (lane == 0) bits[w] = b;
}

// ---------------------------------------------------------------------------
// LayerNorm: one block per row (D=1024), 128 threads, 2 float4 per thread.
// ---------------------------------------------------------------------------
__global__ void __launch_bounds__(128) ln_kernel(const float* __restrict__ x,
                                                 const float* __restrict__ gamma,
                                                 const float* __restrict__ beta,
                                                 float* __restrict__ out)
{
    const int row = blockIdx.x;
    const int t = threadIdx.x;
    const float4* xr = reinterpret_cast<const float4*>(x + (size_t)row * Dv);
    float4 v0 = xr[t], v1 = xr[t + 128];

    float s  = v0.x + v0.y + v0.z + v0.w + v1.x + v1.y + v1.z + v1.w;
    float ss = v0.x*v0.x + v0.y*v0.y + v0.z*v0.z + v0.w*v0.w
             + v1.x*v1.x + v1.y*v1.y + v1.z*v1.z + v1.w*v1.w;

    #pragma unroll
    for (int off = 16; off > 0; off >>= 1) {
        s  += __shfl_xor_sync(0xffffffffu, s,  off);
        ss += __shfl_xor_sync(0xffffffffu, ss, off);
    }
    __shared__ float red[8];
    int warp = t >> 5, lane = t & 31;
    if (lane == 0) { red[warp] = s; red[warp + 4] = ss; }
    __syncthreads();
    s  = red[0] + red[1] + red[2] + red[3];
    ss = red[4] + red[5] + red[6] + red[7];

    const float mean = s * (1.0f / Dv);
    const float var  = ss * (1.0f / Dv) - mean * mean;
    const float rstd = rsqrtf(var + 1e-5f);

    const float4* g4 = reinterpret_cast<const float4*>(gamma);
    const float4* b4 = reinterpret_cast<const float4*>(beta);
    float4* o4 = reinterpret_cast<float4*>(out + (size_t)row * Dv);

    float4 g0 = g4[t], g1 = g4[t + 128];
    float4 e0 = b4[t], e1 = b4[t + 128];
    float4 o;
    o.x = (v0.x - mean) * rstd * g0.x + e0.x;
    o.y = (v0.y - mean) * rstd * g0.y + e0.y;
    o.z = (v0.z - mean) * rstd * g0.z + e0.z;
    o.w = (v0.w - mean) * rstd * g0.w + e0.w;
    o4[t] = o;
    o.x = (v1.x - mean) * rstd * g1.x + e1.x;
    o.y = (v1.y - mean) * rstd * g1.y + e1.y;
    o.z = (v1.z - mean) * rstd * g1.z + e1.z;
    o.w = (v1.w - mean) * rstd * g1.w + e1.w;
    o4[t + 128] = o;
}

// ---------------------------------------------------------------------------
// SGEMM: C[M=4096, N=1024] = A @ W + bias (+ optional residual)
// Tiles: BM=BN=64, BK=16, 256 threads, 4x4 micro-tile per thread.
// ---------------------------------------------------------------------------
template <bool RES>
__global__ void __launch_bounds__(256) gemm64_kernel(const float* __restrict__ A,
                                                     const float* __restrict__ W,
                                                     const float* __restrict__ bias,
                                                     const float* __restrict__ res,
                                                     float* __restrict__ C)
{
    __shared__ float As[64][17];   // pad 17 to kill bank conflicts on column reads
    __shared__ float Bs[16][64];

    const int t  = threadIdx.x;
    const int bm = blockIdx.y * 64;
    const int bn = blockIdx.x * 64;
    const int ty = t >> 4, tx = t & 15;

    const int arow = t >> 2, ac = (t & 3) * 4;   // A-tile loader coords
    const int brow = t >> 4, bc = (t & 15) * 4;  // B-tile loader coords

    const float* Aptr = A + (size_t)(bm + arow) * Dv + ac;
    const float* Wptr = W + (size_t)brow * Dv + bn + bc;

    float acc[4][4];
    #pragma unroll
    for (int i = 0; i < 4; i++)
        #pragma unroll
        for (int j = 0; j < 4; j++) acc[i][j] = 0.0f;

    for (int kt = 0; kt < Dv; kt += 16) {
        float4 av = *reinterpret_cast<const float4*>(Aptr + kt);
        As[arow][ac + 0] = av.x; As[arow][ac + 1] = av.y;
        As[arow][ac + 2] = av.z; As[arow][ac + 3] = av.w;
        *reinterpret_cast<float4*>(&Bs[brow][bc]) =
            *reinterpret_cast<const float4*>(Wptr + (size_t)kt * Dv);
        __syncthreads();

        #pragma unroll
        for (int kk = 0; kk < 16; kk++) {
            float a0 = As[ty * 4 + 0][kk];
            float a1 = As[ty * 4 + 1][kk];
            float a2 = As[ty * 4 + 2][kk];
            float a3 = As[ty * 4 + 3][kk];
            float4 b = *reinterpret_cast<const float4*>(&Bs[kk][tx * 4]);
            acc[0][0] += a0 * b.x; acc[0][1] += a0 * b.y; acc[0][2] += a0 * b.z; acc[0][3] += a0 * b.w;
            acc[1][0] += a1 * b.x; acc[1][1] += a1 * b.y; acc[1][2] += a1 * b.z; acc[1][3] += a1 * b.w;
            acc[2][0] += a2 * b.x; acc[2][1] += a2 * b.y; acc[2][2] += a2 * b.z; acc[2][3] += a2 * b.w;
            acc[3][0] += a3 * b.x; acc[3][1] += a3 * b.y; acc[3][2] += a3 * b.z; acc[3][3] += a3 * b.w;
        }
        __syncthreads();
    }

    const int col = bn + tx * 4;
    float4 bb = *reinterpret_cast<const float4*>(bias + col);
    #pragma unroll
    for (int i = 0; i < 4; i++) {
        const int row = bm + ty * 4 + i;
        float4 o = make_float4(acc[i][0] + bb.x, acc[i][1] + bb.y,
                               acc[i][2] + bb.z, acc[i][3] + bb.w);
        if (RES) {
            float4 r = *reinterpret_cast<const float4*>(res + (size_t)row * Dv + col);
            o.x += r.x; o.y += r.y; o.z += r.z; o.w += r.w;
        }
        *reinterpret_cast<float4*>(C + (size_t)row * Dv + col) = o;
    }
}

// ---------------------------------------------------------------------------
// Attention: flash-style. grid (T/128, H, B), 128 threads.
// Each thread owns one query row (q + acc in registers), all threads stream
// the SAME key j in lockstep -> K/V smem reads are warp-uniform broadcasts.
// Mask comes from the packed bit buffer. Online softmax, rescale only when
// the running max changes (identical math to reference softmax in fp32).
// ---------------------------------------------------------------------------
__global__ void __launch_bounds__(128) attn_kernel(const float* __restrict__ Q,
                                                   const float* __restrict__ K,
                                                   const float* __restrict__ V,
                                                   const unsigned* __restrict__ mbits,
                                                   float* __restrict__ Y)
{
    __shared__ float Ks[64][64];
    __shared__ float Vs[64][64];

    const int b = blockIdx.z, h = blockIdx.y;
    const int t = threadIdx.x;
    const int n = blockIdx.x * 128 + t;

    float q[64];
    {
        const float4* qp = reinterpret_cast<const float4*>(
            Q + ((size_t)(b * Tv + n) * Dv + h * DHv));
        #pragma unroll
        for (int i = 0; i < 16; i++) {
            float4 v = qp[i];
            q[i * 4 + 0] = v.x * 0.125f;   // 1/sqrt(64)
            q[i * 4 + 1] = v.y * 0.125f;
            q[i * 4 + 2] = v.z * 0.125f;
            q[i * 4 + 3] = v.w * 0.125f;
        }
    }
    float acc[64];
    #pragma unroll
    for (int d = 0; d < 64; d++) acc[d] = 0.0f;
    float mrow = -CUDART_INF_F;
    float l = 0.0f;

    const unsigned* row_bits = mbits + (size_t)(b * Tv + n) * (Tv / 32);

    for (int kt = 0; kt < Tv; kt += 64) {
        const float* kbase = K + ((size_t)(b * Tv + kt) * Dv + h * DHv);
        const float* vbase = V + ((size_t)(b * Tv + kt) * Dv + h * DHv);
        #pragma unroll
        for (int i = 0; i < 8; i++) {
            int f = t + i * 128;
            int j = f >> 4, d4 = (f & 15) * 4;
            *reinterpret_cast<float4*>(&Ks[j][d4]) =
                *reinterpret_cast<const float4*>(kbase + (size_t)j * Dv + d4);
            *reinterpret_cast<float4*>(&Vs[j][d4]) =
                *reinterpret_cast<const float4*>(vbase + (size_t)j * Dv + d4);
        }
        __syncthreads();

        const unsigned mb0 = row_bits[(kt >> 5)];
        const unsigned mb1 = row_bits[(kt >> 5) + 1];

        #pragma unroll 2
        for (int j = 0; j < 64; j++) {
            const float4* kr = reinterpret_cast<const float4*>(&Ks[j][0]);
            float s0 = 0.f, s1 = 0.f, s2 = 0.f, s3 = 0.f;
            #pragma unroll
            for (int i = 0; i < 16; i++) {
                float4 kv = kr[i];
                s0 += q[i * 4 + 0] * kv.x;
                s1 += q[i * 4 + 1] * kv.y;
                s2 += q[i * 4 + 2] * kv.z;
                s3 += q[i * 4 + 3] * kv.w;
            }
            float s = (s0 + s1) + (s2 + s3);
            unsigned w = (j & 32) ? mb1 : mb0;
            if (!((w >> (j & 31)) & 1u)) s -= 100000.0f;

            if (s > mrow) {
                float corr = __expf(mrow - s);   // exp(-inf)=0 on first key: safe
                l *= corr;
                #pragma unroll
                for (int d = 0; d < 64; d++) acc[d] *= corr;
                mrow = s;
            }
            float p = __expf(s - mrow);
            l += p;
            const float4* vr = reinterpret_cast<const float4*>(&Vs[j][0]);
            #pragma unroll
            for (int i = 0; i < 16; i++) {
                float4 vv = vr[i];
                acc[i * 4 + 0] += p * vv.x;
                acc[i * 4 + 1] += p * vv.y;
                acc[i * 4 + 2] += p * vv.z;
                acc[i * 4 + 3] += p * vv.w;
            }
        }
        __syncthreads();
    }

    const float inv = 1.0f / l;
    float* yp = Y + ((size_t)(b * Tv + n) * Dv + h * DHv);
    #pragma unroll
    for (int i = 0; i < 16; i++) {
        float4 o = make_float4(acc[i * 4 + 0] * inv, acc[i * 4 + 1] * inv,
                               acc[i * 4 + 2] * inv, acc[i * 4 + 3] * inv);
        *reinterpret_cast<float4*>(yp + i * 4) = o;
    }
}

// ---------------------------------------------------------------------------
extern "C" void kernel_launch(void* const* d_in, const int* in_sizes, int n_in,
                              void* d_out, int out_size)
{
    const float* x        = (const float*)d_in[0];
    const int*   src_mask = (const int*)  d_in[1];
    const float* ln_gamma = (const float*)d_in[2];
    const float* ln_beta  = (const float*)d_in[3];
    const float* Wq = (const float*)d_in[4];
    const float* bq = (const float*)d_in[5];
    const float* Wk = (const float*)d_in[6];
    const float* bk = (const float*)d_in[7];
    const float* Wv = (const float*)d_in[8];
    const float* bv = (const float*)d_in[9];
    const float* Wo = (const float*)d_in[10];
    const float* bo = (const float*)d_in[11];
    float* out = (float*)d_out;

    float *xn, *q, *k, *v, *y;
    unsigned* mbits;
    cudaGetSymbolAddress((void**)&xn,    g_xn);
    cudaGetSymbolAddress((void**)&q,     g_q);
    cudaGetSymbolAddress((void**)&k,     g_k);
    cudaGetSymbolAddress((void**)&v,     g_v);
    cudaGetSymbolAddress((void**)&y,     g_y);
    cudaGetSymbolAddress((void**)&mbits, g_mbits);

    // 1. pack mask bits (262144 words, 8 warps/block)
    pack_mask_kernel<<<NWORDS / 8, 256>>>(src_mask, mbits);

    // 2. LayerNorm
    ln_kernel<<<MROWS, 128>>>(x, ln_gamma, ln_beta, xn);

    // 3. QKV projections
    dim3 gg(Dv / 64, MROWS / 64);   // (16, 64)
    gemm64_kernel<false><<<gg, 256>>>(xn, Wq, bq, nullptr, q);
    gemm64_kernel<false><<<gg, 256>>>(xn, Wk, bk, nullptr, k);
    gemm64_kernel<false><<<gg, 256>>>(xn, Wv, bv, nullptr, v);

    // 4. masked multi-head attention
    dim3 ga(Tv / 128, Hv, Bv);      // (16, 16, 2)
    attn_kernel<<<ga, 128>>>(q, k, v, mbits, y);

    // 5. output projection + residual
    gemm64_kernel<true><<<gg, 256>>>(y, Wo, bo, x, out);
}

// round 7
// speedup vs baseline: 1.3417x; 1.3417x over previous
#include <cuda_runtime.h>
#include <cuda_bf16.h>
#include <math_constants.h>
#include <cstdint>

#define Bv 2
#define Tv 2048
#define Dv 1024
#define Hv 16
#define DHv 64
constexpr int MROWS = Bv * Tv;               // 4096
constexpr int NWORDS = Bv * Tv * (Tv / 32);  // 262144

// ---------------- scratch (__device__ globals; no allocation allowed) -------
__device__ __nv_bfloat16 g_xnhi[MROWS * Dv];
__device__ __nv_bfloat16 g_xnlo[MROWS * Dv];
__device__ __nv_bfloat16 g_wthi[4 * Dv * Dv];   // [Wq^T; Wk^T; Wv^T; Wo^T] rows=[n], cols=[k]
__device__ __nv_bfloat16 g_wtlo[4 * Dv * Dv];
__device__ float g_q[MROWS * Dv];
__device__ float g_k[MROWS * Dv];
__device__ float g_v[MROWS * Dv];
__device__ __nv_bfloat16 g_yhi[MROWS * Dv];
__device__ __nv_bfloat16 g_ylo[MROWS * Dv];
__device__ unsigned g_mbits[NWORDS];

// ---------------- helpers ----------------------------------------------------
__device__ __forceinline__ uint32_t smem_to_u32(const void* p) {
    uint32_t a;
    asm("{ .reg .u64 t; cvta.to.shared.u64 t, %1; cvt.u32.u64 %0, t; }" : "=r"(a) : "l"(p));
    return a;
}

#define SMEM_SWIZZLE_128B(o) ((o) ^ (((o) >> 3) & 0x70))

#define CP_ASYNC16(smem_u32, gptr) \
    asm volatile("cp.async.cg.shared.global [%0], [%1], 16;" \
                 :: "r"(smem_u32), "l"(gptr) : "memory")
#define CP_COMMIT() asm volatile("cp.async.commit_group;" ::: "memory")
#define CP_WAIT(n)  asm volatile("cp.async.wait_group %0;" :: "n"(n) : "memory")

__device__ __forceinline__ void ldsm4(uint32_t addr, uint32_t& r0, uint32_t& r1,
                                      uint32_t& r2, uint32_t& r3) {
    asm volatile("ldmatrix.sync.aligned.m8n8.x4.shared.b16 {%0,%1,%2,%3}, [%4];"
                 : "=r"(r0), "=r"(r1), "=r"(r2), "=r"(r3) : "r"(addr));
}

__device__ __forceinline__ void mma16816(float* c, const uint32_t* a, const uint32_t* b) {
    asm volatile(
        "mma.sync.aligned.m16n8k16.row.col.f32.bf16.bf16.f32 "
        "{%0,%1,%2,%3}, {%4,%5,%6,%7}, {%8,%9}, {%0,%1,%2,%3};"
        : "+f"(c[0]), "+f"(c[1]), "+f"(c[2]), "+f"(c[3])
        : "r"(a[0]), "r"(a[1]), "r"(a[2]), "r"(a[3]), "r"(b[0]), "r"(b[1]));
}

// ---------------- hi/lo bf16 split helpers ----------------------------------
__device__ __forceinline__ void store_hilo4(__nv_bfloat16* Hi, __nv_bfloat16* Lo,
                                            size_t idx, float4 o) {
    __nv_bfloat16 h0 = __float2bfloat16(o.x), h1 = __float2bfloat16(o.y);
    __nv_bfloat16 h2 = __float2bfloat16(o.z), h3 = __float2bfloat16(o.w);
    float l0 = o.x - __bfloat162float(h0), l1 = o.y - __bfloat162float(h1);
    float l2 = o.z - __bfloat162float(h2), l3 = o.w - __bfloat162float(h3);
    __nv_bfloat162 a, b, c, d;
    a.x = h0; a.y = h1; b.x = h2; b.y = h3;
    c.x = __float2bfloat16(l0); c.y = __float2bfloat16(l1);
    d.x = __float2bfloat16(l2); d.y = __float2bfloat16(l3);
    uint2 hv, lv;
    hv.x = *reinterpret_cast<uint32_t*>(&a); hv.y = *reinterpret_cast<uint32_t*>(&b);
    lv.x = *reinterpret_cast<uint32_t*>(&c); lv.y = *reinterpret_cast<uint32_t*>(&d);
    *reinterpret_cast<uint2*>(Hi + idx) = hv;
    *reinterpret_cast<uint2*>(Lo + idx) = lv;
}

// ---------------------------------------------------------------------------
// Pack src_mask into bitmask words (bit set = attend)
// ---------------------------------------------------------------------------
__global__ void __launch_bounds__(256) pack_mask_kernel(const int* __restrict__ mask,
                                                        unsigned* __restrict__ bits)
{
    int w = blockIdx.x * (blockDim.x >> 5) + (threadIdx.x >> 5);
    int lane = threadIdx.x & 31;
    int v = mask[(size_t)w * 32 + lane];
    unsigned b = __ballot_sync(0xffffffffu, v != 0);
    if (lane == 0) bits[w] = b;
}

// ---------------------------------------------------------------------------
// LayerNorm -> bf16 hi/lo split output
// ---------------------------------------------------------------------------
__global__ void __launch_bounds__(128) ln_kernel(const float* __restrict__ x,
                                                 const float* __restrict__ gamma,
                                                 const float* __restrict__ beta,
                                                 __nv_bfloat16* __restrict__ ohi,
                                                 __nv_bfloat16* __restrict__ olo)
{
    const int row = blockIdx.x;
    const int t = threadIdx.x;
    const float4* xr = reinterpret_cast<const float4*>(x + (size_t)row * Dv);
    float4 v0 = xr[t], v1 = xr[t + 128];

    float s  = v0.x + v0.y + v0.z + v0.w + v1.x + v1.y + v1.z + v1.w;
    float ss = v0.x*v0.x + v0.y*v0.y + v0.z*v0.z + v0.w*v0.w
             + v1.x*v1.x + v1.y*v1.y + v1.z*v1.z + v1.w*v1.w;

    #pragma unroll
    for (int off = 16; off > 0; off >>= 1) {
        s  += __shfl_xor_sync(0xffffffffu, s,  off);
        ss += __shfl_xor_sync(0xffffffffu, ss, off);
    }
    __shared__ float red[8];
    int warp = t >> 5, lane = t & 31;
    if (lane == 0) { red[warp] = s; red[warp + 4] = ss; }
    __syncthreads();
    s  = red[0] + red[1] + red[2] + red[3];
    ss = red[4] + red[5] + red[6] + red[7];

    const float mean = s * (1.0f / Dv);
    const float var  = ss * (1.0f / Dv) - mean * mean;
    const float rstd = rsqrtf(var + 1e-5f);

    const float4* g4 = reinterpret_cast<const float4*>(gamma);
    const float4* b4 = reinterpret_cast<const float4*>(beta);
    float4 g0 = g4[t], g1 = g4[t + 128];
    float4 e0 = b4[t], e1 = b4[t + 128];
    float4 o;
    o.x = (v0.x - mean) * rstd * g0.x + e0.x;
    o.y = (v0.y - mean) * rstd * g0.y + e0.y;
    o.z = (v0.z - mean) * rstd * g0.z + e0.z;
    o.w = (v0.w - mean) * rstd * g0.w + e0.w;
    store_hilo4(ohi, olo, (size_t)row * Dv + t * 4, o);
    o.x = (v1.x - mean) * rstd * g1.x + e1.x;
    o.y = (v1.y - mean) * rstd * g1.y + e1.y;
    o.z = (v1.z - mean) * rstd * g1.z + e1.z;
    o.w = (v1.w - mean) * rstd * g1.w + e1.w;
    store_hilo4(ohi, olo, (size_t)row * Dv + (t + 128) * 4, o);
}

// ---------------------------------------------------------------------------
// Weight transpose + bf16 hi/lo conversion: g_wt[z*1024 + n][k] = W_z[k][n]
// ---------------------------------------------------------------------------
__global__ void __launch_bounds__(256) wconv_kernel(const float* __restrict__ w0,
                                                    const float* __restrict__ w1,
                                                    const float* __restrict__ w2,
                                                    const float* __restrict__ w3)
{
    __shared__ float tile[32][33];
    const float* src = (blockIdx.z == 0) ? w0 : (blockIdx.z == 1) ? w1
                     : (blockIdx.z == 2) ? w2 : w3;
    int kt = blockIdx.x * 32, nt = blockIdx.y * 32;
    int tx = threadIdx.x & 31, ty = threadIdx.x >> 5;
    #pragma unroll
    for (int i = 0; i < 4; i++)
        tile[ty + 8 * i][tx] = src[(size_t)(kt + ty + 8 * i) * Dv + nt + tx];
    __syncthreads();
    size_t off = (size_t)blockIdx.z * Dv;
    #pragma unroll
    for (int i = 0; i < 4; i++) {
        int n = nt + ty + 8 * i, kk = kt + tx;
        float v = tile[tx][ty + 8 * i];
        __nv_bfloat16 hi = __float2bfloat16(v);
        float lof = v - __bfloat162float(hi);
        g_wthi[(off + n) * Dv + kk] = hi;
        g_wtlo[(off + n) * Dv + kk] = __float2bfloat16(lof);
    }
}

// ---------------------------------------------------------------------------
// mma.sync bf16-split GEMM. CTA tile 128x128, 8 warps (2x4), K-chunk 64,
// double-buffered cp.async, SW128-swizzled smem, ldmatrix fragments.
//   C = Ahi@Bhi^T + Ahi@Blo^T + Alo@Bhi^T   (fp32 accum)
// Epilogue: + bias (+ residual), direct fp32 stores.
// ---------------------------------------------------------------------------
constexpr int STAGE = 65536;                 // Ahi|Alo|Whi|Wlo tiles (16KB each)
constexpr int SMEM_DYN = 2 * STAGE + 1024;

__global__ void __launch_bounds__(256) gemm_tc_kernel(
    const __nv_bfloat16* __restrict__ Ahi, const __nv_bfloat16* __restrict__ Alo,
    int wrow_off,
    float* c0, const float* b0, float* c1, const float* b1,
    float* c2, const float* b2, const float* res)
{
    extern __shared__ char dyns[];
    const uint32_t sraw = smem_to_u32(dyns);
    const uint32_t s0 = (sraw + 1023) & ~1023u;

    const int tid = threadIdx.x;
    const int bm = blockIdx.y * 128;
    const int bx = blockIdx.x;
    const int wrow = wrow_off + bx * 128;

    float acc[4][4][4];
    #pragma unroll
    for (int i = 0; i < 4; i++)
        #pragma unroll
        for (int j = 0; j < 4; j++)
            #pragma unroll
            for (int r = 0; r < 4; r++) acc[i][j][r] = 0.0f;

    // ---- producer: cp.async 16B x 16 per thread per chunk ----
    const int lr  = tid >> 3;          // base row 0..31
    const int lc8 = (tid & 7) * 8;     // bf16 col within 64-wide chunk
    const uint32_t lcb = (tid & 7) * 16;

    auto issue_loads = [&](int c, int st) {
        const uint32_t sb = s0 + st * STAGE;
        #pragma unroll
        for (int i = 0; i < 4; i++) {
            const int r = lr + 32 * i;
            const uint32_t sw = SMEM_SWIZZLE_128B((uint32_t)(r * 128) + lcb);
            const size_t ga = (size_t)(bm + r) * Dv + c * 64 + lc8;
            const size_t gw = (size_t)(wrow + r) * Dv + c * 64 + lc8;
            CP_ASYNC16(sb + sw,          (const void*)(Ahi + ga));
            CP_ASYNC16(sb + 16384 + sw,  (const void*)(Alo + ga));
            CP_ASYNC16(sb + 32768 + sw,  (const void*)(g_wthi + gw));
            CP_ASYNC16(sb + 49152 + sw,  (const void*)(g_wtlo + gw));
        }
    };

    // ---- consumer: ldmatrix + mma ----
    const int l = tid & 31;
    const int w = tid >> 5;
    const int wm = (w >> 2) * 64;      // warp m offset (0/64)
    const int wn = (w & 3) * 32;       // warp n offset (0/32/64/96)

    auto compute = [&](int st) {
        const uint32_t sb = s0 + st * STAGE;
        #pragma unroll
        for (int ks = 0; ks < 4; ks++) {
            uint32_t ah[4][4], al[4][4], bh[4][2], bl[4][2];
            // A fragments: m16k16 via ldmatrix.x4
            const int akb = ks * 32 + ((l >> 4) & 1) * 16;
            #pragma unroll
            for (int mt = 0; mt < 4; mt++) {
                const int row = wm + mt * 16 + (l & 7) + ((l >> 3) & 1) * 8;
                const uint32_t off = SMEM_SWIZZLE_128B((uint32_t)(row * 128 + akb));
                ldsm4(sb + off,         ah[mt][0], ah[mt][1], ah[mt][2], ah[mt][3]);
                ldsm4(sb + 16384 + off, al[mt][0], al[mt][1], al[mt][2], al[mt][3]);
            }
            // B fragments: two n8-tiles per ldmatrix.x4
            const int bkb = ks * 32 + ((l >> 3) & 1) * 16;
            #pragma unroll
            for (int j = 0; j < 2; j++) {
                const int nr = wn + j * 16 + (l & 7) + ((l >> 4) & 1) * 8;
                const uint32_t off = SMEM_SWIZZLE_128B((uint32_t)(nr * 128 + bkb));
                uint32_t r0, r1, r2, r3;
                ldsm4(sb + 32768 + off, r0, r1, r2, r3);
                bh[2 * j][0] = r0; bh[2 * j][1] = r1;
                bh[2 * j + 1][0] = r2; bh[2 * j + 1][1] = r3;
                ldsm4(sb + 49152 + off, r0, r1, r2, r3);
                bl[2 * j][0] = r0; bl[2 * j][1] = r1;
                bl[2 * j + 1][0] = r2; bl[2 * j + 1][1] = r3;
            }
            #pragma unroll
            for (int mt = 0; mt < 4; mt++)
                #pragma unroll
                for (int nt = 0; nt < 4; nt++) {
                    mma16816(acc[mt][nt], ah[mt], bh[nt]);
                    mma16816(acc[mt][nt], ah[mt], bl[nt]);
                    mma16816(acc[mt][nt], al[mt], bh[nt]);
                }
        }
    };

    issue_loads(0, 0); CP_COMMIT();
    #pragma unroll 1
    for (int c = 0; c < 16; c++) {
        if (c < 15) { issue_loads(c + 1, (c + 1) & 1); CP_COMMIT(); CP_WAIT(1); }
        else        { CP_WAIT(0); }
        __syncthreads();
        compute(c & 1);
        __syncthreads();
    }

    // ---- epilogue ----
    const int seg = bx >> 3;
    float* C; const float* bias;
    if (seg == 0)      { C = c0; bias = b0; }
    else if (seg == 1) { C = c1; bias = b1; }
    else               { C = c2; bias = b2; }
    const int coll = (bx & 7) * 128;

    #pragma unroll
    for (int mt = 0; mt < 4; mt++) {
        #pragma unroll
        for (int nt = 0; nt < 4; nt++) {
            const int row = bm + wm + mt * 16 + (l >> 2);
            const int col = coll + wn + nt * 8 + (l & 3) * 2;
            float2 bb = *reinterpret_cast<const float2*>(bias + col);
            float2 v0 = make_float2(acc[mt][nt][0] + bb.x, acc[mt][nt][1] + bb.y);
            float2 v1 = make_float2(acc[mt][nt][2] + bb.x, acc[mt][nt][3] + bb.y);
            const size_t g0o = (size_t)row * Dv + col;
            const size_t g1o = (size_t)(row + 8) * Dv + col;
            if (res) {
                float2 r0 = *reinterpret_cast<const float2*>(res + g0o);
                float2 r1 = *reinterpret_cast<const float2*>(res + g1o);
                v0.x += r0.x; v0.y += r0.y; v1.x += r1.x; v1.y += r1.y;
            }
            *reinterpret_cast<float2*>(C + g0o) = v0;
            *reinterpret_cast<float2*>(C + g1o) = v1;
        }
    }
}

// ---------------------------------------------------------------------------
// Attention (scalar flash-style, identical math to the passing R0 kernel);
// epilogue emits bf16 hi/lo y for the tensor-core O projection.
// ---------------------------------------------------------------------------
__global__ void __launch_bounds__(128) attn_kernel(const float* __restrict__ Q,
                                                   const float* __restrict__ K,
                                                   const float* __restrict__ V,
                                                   const unsigned* __restrict__ mbits,
                                                   __nv_bfloat16* __restrict__ Yhi,
                                                   __nv_bfloat16* __restrict__ Ylo)
{
    __shared__ float Ks[64][64];
    __shared__ float Vs[64][64];

    const int b = blockIdx.z, h = blockIdx.y;
    const int t = threadIdx.x;
    const int n = blockIdx.x * 128 + t;

    float q[64];
    {
        const float4* qp = reinterpret_cast<const float4*>(
            Q + ((size_t)(b * Tv + n) * Dv + h * DHv));
        #pragma unroll
        for (int i = 0; i < 16; i++) {
            float4 v = qp[i];
            q[i * 4 + 0] = v.x * 0.125f;
            q[i * 4 + 1] = v.y * 0.125f;
            q[i * 4 + 2] = v.z * 0.125f;
            q[i * 4 + 3] = v.w * 0.125f;
        }
    }
    float acc[64];
    #pragma unroll
    for (int d = 0; d < 64; d++) acc[d] = 0.0f;
    float mrow = -CUDART_INF_F;
    float l = 0.0f;

    const unsigned* row_bits = mbits + (size_t)(b * Tv + n) * (Tv / 32);

    for (int kt = 0; kt < Tv; kt += 64) {
        const float* kbase = K + ((size_t)(b * Tv + kt) * Dv + h * DHv);
        const float* vbase = V + ((size_t)(b * Tv + kt) * Dv + h * DHv);
        #pragma unroll
        for (int i = 0; i < 8; i++) {
            int f = t + i * 128;
            int j = f >> 4, d4 = (f & 15) * 4;
            *reinterpret_cast<float4*>(&Ks[j][d4]) =
                *reinterpret_cast<const float4*>(kbase + (size_t)j * Dv + d4);
            *reinterpret_cast<float4*>(&Vs[j][d4]) =
                *reinterpret_cast<const float4*>(vbase + (size_t)j * Dv + d4);
        }
        __syncthreads();

        const unsigned mb0 = row_bits[(kt >> 5)];
        const unsigned mb1 = row_bits[(kt >> 5) + 1];

        #pragma unroll 2
        for (int j = 0; j < 64; j++) {
            const float4* kr = reinterpret_cast<const float4*>(&Ks[j][0]);
            float s0 = 0.f, s1 = 0.f, s2 = 0.f, s3 = 0.f;
            #pragma unroll
            for (int i = 0; i < 16; i++) {
                float4 kv = kr[i];
                s0 += q[i * 4 + 0] * kv.x;
                s1 += q[i * 4 + 1] * kv.y;
                s2 += q[i * 4 + 2] * kv.z;
                s3 += q[i * 4 + 3] * kv.w;
            }
            float s = (s0 + s1) + (s2 + s3);
            unsigned w = (j & 32) ? mb1 : mb0;
            if (!((w >> (j & 31)) & 1u)) s -= 100000.0f;

            if (s > mrow) {
                float corr = __expf(mrow - s);
                l *= corr;
                #pragma unroll
                for (int d = 0; d < 64; d++) acc[d] *= corr;
                mrow = s;
            }
            float p = __expf(s - mrow);
            l += p;
            const float4* vr = reinterpret_cast<const float4*>(&Vs[j][0]);
            #pragma unroll
            for (int i = 0; i < 16; i++) {
                float4 vv = vr[i];
                acc[i * 4 + 0] += p * vv.x;
                acc[i * 4 + 1] += p * vv.y;
                acc[i * 4 + 2] += p * vv.z;
                acc[i * 4 + 3] += p * vv.w;
            }
        }
        __syncthreads();
    }

    const float inv = 1.0f / l;
    const size_t ybase = (size_t)(b * Tv + n) * Dv + h * DHv;
    #pragma unroll
    for (int i = 0; i < 16; i++) {
        float4 o = make_float4(acc[i * 4 + 0] * inv, acc[i * 4 + 1] * inv,
                               acc[i * 4 + 2] * inv, acc[i * 4 + 3] * inv);
        store_hilo4(Yhi, Ylo, ybase + i * 4, o);
    }
}

// ---------------------------------------------------------------------------
extern "C" void kernel_launch(void* const* d_in, const int* in_sizes, int n_in,
                              void* d_out, int out_size)
{
    const float* x        = (const float*)d_in[0];
    const int*   src_mask = (const int*)  d_in[1];
    const float* ln_gamma = (const float*)d_in[2];
    const float* ln_beta  = (const float*)d_in[3];
    const float* Wq = (const float*)d_in[4];
    const float* bq = (const float*)d_in[5];
    const float* Wk = (const float*)d_in[6];
    const float* bk = (const float*)d_in[7];
    const float* Wv = (const float*)d_in[8];
    const float* bv = (const float*)d_in[9];
    const float* Wo = (const float*)d_in[10];
    const float* bo = (const float*)d_in[11];
    float* out = (float*)d_out;

    __nv_bfloat16 *xnhi, *xnlo, *yhi, *ylo;
    float *q, *k, *v;
    unsigned* mbits;
    cudaGetSymbolAddress((void**)&xnhi,  g_xnhi);
    cudaGetSymbolAddress((void**)&xnlo,  g_xnlo);
    cudaGetSymbolAddress((void**)&yhi,   g_yhi);
    cudaGetSymbolAddress((void**)&ylo,   g_ylo);
    cudaGetSymbolAddress((void**)&q,     g_q);
    cudaGetSymbolAddress((void**)&k,     g_k);
    cudaGetSymbolAddress((void**)&v,     g_v);
    cudaGetSymbolAddress((void**)&mbits, g_mbits);

    cudaFuncSetAttribute(gemm_tc_kernel, cudaFuncAttributeMaxDynamicSharedMemorySize, SMEM_DYN);

    // 1. pack mask bits
    pack_mask_kernel<<<NWORDS / 8, 256>>>(src_mask, mbits);

    // 2. LayerNorm -> bf16 hi/lo
    ln_kernel<<<MROWS, 128>>>(x, ln_gamma, ln_beta, xnhi, xnlo);

    // 3. weight transpose + hi/lo conversion (Wq, Wk, Wv, Wo)
    wconv_kernel<<<dim3(Dv / 32, Dv / 32, 4), 256>>>(Wq, Wk, Wv, Wo);

    // 4. fused QKV projection on tensor cores (N = 3072)
    gemm_tc_kernel<<<dim3(24, 32), 256, SMEM_DYN>>>(xnhi, xnlo, 0,
                                                    q, bq, k, bk, v, bv, nullptr);

    // 5. masked multi-head attention (emits y as bf16 hi/lo)
    dim3 ga(Tv / 128, Hv, Bv);
    attn_kernel<<<ga, 128>>>(q, k, v, mbits, yhi, ylo);

    // 6. output projection + bias + residual on tensor cores
    gemm_tc_kernel<<<dim3(8, 32), 256, SMEM_DYN>>>(yhi, ylo, 3072,
                                                   out, bo, out, bo, out, bo, x);
}

// round 8
// speedup vs baseline: 3.3755x; 2.5158x over previous
#include <cuda_runtime.h>
#include <cuda_bf16.h>
#include <math_constants.h>
#include <cstdint>

#define Bv 2
#define Tv 2048
#define Dv 1024
#define Hv 16
#define DHv 64
constexpr int MROWS = Bv * Tv;               // 4096
constexpr int NWORDS = Bv * Tv * (Tv / 32);  // 262144

// ---------------- scratch (__device__ globals; no allocation allowed) -------
__device__ __nv_bfloat16 g_xnhi[MROWS * Dv];
__device__ __nv_bfloat16 g_xnlo[MROWS * Dv];
__device__ __nv_bfloat16 g_wthi[4 * Dv * Dv];   // [Wq^T; Wk^T; Wv^T; Wo^T] rows=[n], cols=[k]
__device__ __nv_bfloat16 g_wtlo[4 * Dv * Dv];
__device__ __nv_bfloat16 g_qkvhi[(size_t)MROWS * 3072];  // [row][q|k|v]
__device__ __nv_bfloat16 g_qkvlo[(size_t)MROWS * 3072];
__device__ __nv_bfloat16 g_yhi[MROWS * Dv];
__device__ __nv_bfloat16 g_ylo[MROWS * Dv];
__device__ unsigned g_mbits[NWORDS];

// ---------------- helpers ----------------------------------------------------
__device__ __forceinline__ uint32_t smem_to_u32(const void* p) {
    uint32_t a;
    asm("{ .reg .u64 t; cvta.to.shared.u64 t, %1; cvt.u32.u64 %0, t; }" : "=r"(a) : "l"(p));
    return a;
}

#define SMEM_SWIZZLE_128B(o) ((o) ^ (((o) >> 3) & 0x70))

#define CP_ASYNC16(smem_u32, gptr) \
    asm volatile("cp.async.cg.shared.global [%0], [%1], 16;" \
                 :: "r"(smem_u32), "l"(gptr) : "memory")
#define CP_COMMIT() asm volatile("cp.async.commit_group;" ::: "memory")
#define CP_WAIT(n)  asm volatile("cp.async.wait_group %0;" :: "n"(n) : "memory")

__device__ __forceinline__ void ldsm4(uint32_t addr, uint32_t& r0, uint32_t& r1,
                                      uint32_t& r2, uint32_t& r3) {
    asm volatile("ldmatrix.sync.aligned.m8n8.x4.shared.b16 {%0,%1,%2,%3}, [%4];"
                 : "=r"(r0), "=r"(r1), "=r"(r2), "=r"(r3) : "r"(addr));
}
__device__ __forceinline__ void ldsm4t(uint32_t addr, uint32_t& r0, uint32_t& r1,
                                       uint32_t& r2, uint32_t& r3) {
    asm volatile("ldmatrix.sync.aligned.m8n8.x4.trans.shared.b16 {%0,%1,%2,%3}, [%4];"
                 : "=r"(r0), "=r"(r1), "=r"(r2), "=r"(r3) : "r"(addr));
}

__device__ __forceinline__ void mma16816(float* c, const uint32_t* a, const uint32_t* b) {
    asm volatile(
        "mma.sync.aligned.m16n8k16.row.col.f32.bf16.bf16.f32 "
        "{%0,%1,%2,%3}, {%4,%5,%6,%7}, {%8,%9}, {%0,%1,%2,%3};"
        : "+f"(c[0]), "+f"(c[1]), "+f"(c[2]), "+f"(c[3])
        : "r"(a[0]), "r"(a[1]), "r"(a[2]), "r"(a[3]), "r"(b[0]), "r"(b[1]));
}

// split a float pair into packed bf16 hi + bf16 lo (residual) words
__device__ __forceinline__ void split2(float a, float b, uint32_t& hi, uint32_t& lo) {
    __nv_bfloat162 h = __floats2bfloat162_rn(a, b);
    float la = a - __bfloat162float(h.x);
    float lb = b - __bfloat162float(h.y);
    __nv_bfloat162 l2 = __floats2bfloat162_rn(la, lb);
    hi = *reinterpret_cast<uint32_t*>(&h);
    lo = *reinterpret_cast<uint32_t*>(&l2);
}

__device__ __forceinline__ void store_hilo4(__nv_bfloat16* Hi, __nv_bfloat16* Lo,
                                            size_t idx, float4 o) {
    uint32_t h0, l0, h1, l1;
    split2(o.x, o.y, h0, l0);
    split2(o.z, o.w, h1, l1);
    uint2 hv = make_uint2(h0, h1), lv = make_uint2(l0, l1);
    *reinterpret_cast<uint2*>(Hi + idx) = hv;
    *reinterpret_cast<uint2*>(Lo + idx) = lv;
}

// ---------------------------------------------------------------------------
// Pack src_mask into bitmask words (bit set = attend)
// ---------------------------------------------------------------------------
__global__ void __launch_bounds__(256) pack_mask_kernel(const int* __restrict__ mask,
                                                        unsigned* __restrict__ bits)
{
    int w = blockIdx.x * (blockDim.x >> 5) + (threadIdx.x >> 5);
    int lane = threadIdx.x & 31;
    int v = mask[(size_t)w * 32 + lane];
    unsigned b = __ballot_sync(0xffffffffu, v != 0);
    if (lane == 0) bits[w] = b;
}

// ---------------------------------------------------------------------------
// LayerNorm -> bf16 hi/lo split output
// ---------------------------------------------------------------------------
__global__ void __launch_bounds__(128) ln_kernel(const float* __restrict__ x,
                                                 const float* __restrict__ gamma,
                                                 const float* __restrict__ beta,
                                                 __nv_bfloat16* __restrict__ ohi,
                                                 __nv_bfloat16* __restrict__ olo)
{
    const int row = blockIdx.x;
    const int t = threadIdx.x;
    const float4* xr = reinterpret_cast<const float4*>(x + (size_t)row * Dv);
    float4 v0 = xr[t], v1 = xr[t + 128];

    float s  = v0.x + v0.y + v0.z + v0.w + v1.x + v1.y + v1.z + v1.w;
    float ss = v0.x*v0.x + v0.y*v0.y + v0.z*v0.z + v0.w*v0.w
             + v1.x*v1.x + v1.y*v1.y + v1.z*v1.z + v1.w*v1.w;

    #pragma unroll
    for (int off = 16; off > 0; off >>= 1) {
        s  += __shfl_xor_sync(0xffffffffu, s,  off);
        ss += __shfl_xor_sync(0xffffffffu, ss, off);
    }
    __shared__ float red[8];
    int warp = t >> 5, lane = t & 31;
    if (lane == 0) { red[warp] = s; red[warp + 4] = ss; }
    __syncthreads();
    s  = red[0] + red[1] + red[2] + red[3];
    ss = red[4] + red[5] + red[6] + red[7];

    const float mean = s * (1.0f / Dv);
    const float var  = ss * (1.0f / Dv) - mean * mean;
    const float rstd = rsqrtf(var + 1e-5f);

    const float4* g4 = reinterpret_cast<const float4*>(gamma);
    const float4* b4 = reinterpret_cast<const float4*>(beta);
    float4 g0 = g4[t], g1 = g4[t + 128];
    float4 e0 = b4[t], e1 = b4[t + 128];
    float4 o;
    o.x = (v0.x - mean) * rstd * g0.x + e0.x;
    o.y = (v0.y - mean) * rstd * g0.y + e0.y;
    o.z = (v0.z - mean) * rstd * g0.z + e0.z;
    o.w = (v0.w - mean) * rstd * g0.w + e0.w;
    store_hilo4(ohi, olo, (size_t)row * Dv + t * 4, o);
    o.x = (v1.x - mean) * rstd * g1.x + e1.x;
    o.y = (v1.y - mean) * rstd * g1.y + e1.y;
    o.z = (v1.z - mean) * rstd * g1.z + e1.z;
    o.w = (v1.w - mean) * rstd * g1.w + e1.w;
    store_hilo4(ohi, olo, (size_t)row * Dv + (t + 128) * 4, o);
}

// ---------------------------------------------------------------------------
// Weight transpose + bf16 hi/lo conversion: g_wt[z*1024 + n][k] = W_z[k][n]
// ---------------------------------------------------------------------------
__global__ void __launch_bounds__(256) wconv_kernel(const float* __restrict__ w0,
                                                    const float* __restrict__ w1,
                                                    const float* __restrict__ w2,
                                                    const float* __restrict__ w3)
{
    __shared__ float tile[32][33];
    const float* src = (blockIdx.z == 0) ? w0 : (blockIdx.z == 1) ? w1
                     : (blockIdx.z == 2) ? w2 : w3;
    int kt = blockIdx.x * 32, nt = blockIdx.y * 32;
    int tx = threadIdx.x & 31, ty = threadIdx.x >> 5;
    #pragma unroll
    for (int i = 0; i < 4; i++)
        tile[ty + 8 * i][tx] = src[(size_t)(kt + ty + 8 * i) * Dv + nt + tx];
    __syncthreads();
    size_t off = (size_t)blockIdx.z * Dv;
    #pragma unroll
    for (int i = 0; i < 4; i++) {
        int n = nt + ty + 8 * i, kk = kt + tx;
        float v = tile[tx][ty + 8 * i];
        __nv_bfloat16 hi = __float2bfloat16(v);
        float lof = v - __bfloat162float(hi);
        g_wthi[(off + n) * Dv + kk] = hi;
        g_wtlo[(off + n) * Dv + kk] = __float2bfloat16(lof);
    }
}

// ---------------------------------------------------------------------------
// mma.sync bf16-split GEMM. CTA tile 128x128, 8 warps (2x4), K-chunk 64,
// double-buffered cp.async, SW128-swizzled smem, ldmatrix fragments.
//   C = Ahi@Bhi^T + Ahi@Blo^T + Alo@Bhi^T   (fp32 accum)
// HILO=true : epilogue emits bf16 hi/lo into g_qkv (stride 3072),
//             segment 0 (q) pre-scaled by 0.125. bias per 1024-col segment.
// HILO=false: epilogue writes fp32 (+bias +residual), stride 1024.
// ---------------------------------------------------------------------------
constexpr int STAGE = 65536;                 // Ahi|Alo|Whi|Wlo tiles (16KB each)
constexpr int SMEM_DYN = 2 * STAGE + 1024;

template <bool HILO>
__global__ void __launch_bounds__(256) gemm_tc_kernel(
    const __nv_bfloat16* __restrict__ Ahi, const __nv_bfloat16* __restrict__ Alo,
    int wrow_off,
    float* Cf, const float* res,
    __nv_bfloat16* Chi, __nv_bfloat16* Clo,
    const float* b0, const float* b1, const float* b2)
{
    extern __shared__ char dyns[];
    const uint32_t sraw = smem_to_u32(dyns);
    const uint32_t s0 = (sraw + 1023) & ~1023u;

    const int tid = threadIdx.x;
    const int bm = blockIdx.y * 128;
    const int bx = blockIdx.x;
    const int wrow = wrow_off + bx * 128;

    float acc[4][4][4];
    #pragma unroll
    for (int i = 0; i < 4; i++)
        #pragma unroll
        for (int j = 0; j < 4; j++)
            #pragma unroll
            for (int r = 0; r < 4; r++) acc[i][j][r] = 0.0f;

    const int lr  = tid >> 3;
    const int lc8 = (tid & 7) * 8;
    const uint32_t lcb = (tid & 7) * 16;

    auto issue_loads = [&](int c, int st) {
        const uint32_t sb = s0 + st * STAGE;
        #pragma unroll
        for (int i = 0; i < 4; i++) {
            const int r = lr + 32 * i;
            const uint32_t sw = SMEM_SWIZZLE_128B((uint32_t)(r * 128) + lcb);
            const size_t ga = (size_t)(bm + r) * Dv + c * 64 + lc8;
            const size_t gw = (size_t)(wrow + r) * Dv + c * 64 + lc8;
            CP_ASYNC16(sb + sw,          (const void*)(Ahi + ga));
            CP_ASYNC16(sb + 16384 + sw,  (const void*)(Alo + ga));
            CP_ASYNC16(sb + 32768 + sw,  (const void*)(g_wthi + gw));
            CP_ASYNC16(sb + 49152 + sw,  (const void*)(g_wtlo + gw));
        }
    };

    const int l = tid & 31;
    const int w = tid >> 5;
    const int wm = (w >> 2) * 64;
    const int wn = (w & 3) * 32;

    auto compute = [&](int st) {
        const uint32_t sb = s0 + st * STAGE;
        #pragma unroll
        for (int ks = 0; ks < 4; ks++) {
            uint32_t ah[4][4], al[4][4], bh[4][2], bl[4][2];
            const int akb = ks * 32 + ((l >> 4) & 1) * 16;
            #pragma unroll
            for (int mt = 0; mt < 4; mt++) {
                const int row = wm + mt * 16 + (l & 7) + ((l >> 3) & 1) * 8;
                const uint32_t off = SMEM_SWIZZLE_128B((uint32_t)(row * 128 + akb));
                ldsm4(sb + off,         ah[mt][0], ah[mt][1], ah[mt][2], ah[mt][3]);
                ldsm4(sb + 16384 + off, al[mt][0], al[mt][1], al[mt][2], al[mt][3]);
            }
            const int bkb = ks * 32 + ((l >> 3) & 1) * 16;
            #pragma unroll
            for (int j = 0; j < 2; j++) {
                const int nr = wn + j * 16 + (l & 7) + ((l >> 4) & 1) * 8;
                const uint32_t off = SMEM_SWIZZLE_128B((uint32_t)(nr * 128 + bkb));
                uint32_t r0, r1, r2, r3;
                ldsm4(sb + 32768 + off, r0, r1, r2, r3);
                bh[2 * j][0] = r0; bh[2 * j][1] = r1;
                bh[2 * j + 1][0] = r2; bh[2 * j + 1][1] = r3;
                ldsm4(sb + 49152 + off, r0, r1, r2, r3);
                bl[2 * j][0] = r0; bl[2 * j][1] = r1;
                bl[2 * j + 1][0] = r2; bl[2 * j + 1][1] = r3;
            }
            #pragma unroll
            for (int mt = 0; mt < 4; mt++)
                #pragma unroll
                for (int nt = 0; nt < 4; nt++) {
                    mma16816(acc[mt][nt], ah[mt], bh[nt]);
                    mma16816(acc[mt][nt], ah[mt], bl[nt]);
                    mma16816(acc[mt][nt], al[mt], bh[nt]);
                }
        }
    };

    issue_loads(0, 0); CP_COMMIT();
    #pragma unroll 1
    for (int c = 0; c < 16; c++) {
        if (c < 15) { issue_loads(c + 1, (c + 1) & 1); CP_COMMIT(); CP_WAIT(1); }
        else        { CP_WAIT(0); }
        __syncthreads();
        compute(c & 1);
        __syncthreads();
    }

    // ---- epilogue ----
    const int seg = bx >> 3;
    const float* bias = (seg == 0) ? b0 : (seg == 1) ? b1 : b2;
    const float scale = (HILO && seg == 0) ? 0.125f : 1.0f;

    #pragma unroll
    for (int mt = 0; mt < 4; mt++) {
        #pragma unroll
        for (int nt = 0; nt < 4; nt++) {
            const int row = bm + wm + mt * 16 + (l >> 2);
            const int cseg = (bx & 7) * 128 + wn + nt * 8 + (l & 3) * 2;  // col within segment
            float2 bb = *reinterpret_cast<const float2*>(bias + cseg);
            float v0 = (acc[mt][nt][0] + bb.x) * scale;
            float v1 = (acc[mt][nt][1] + bb.y) * scale;
            float v2 = (acc[mt][nt][2] + bb.x) * scale;
            float v3 = (acc[mt][nt][3] + bb.y) * scale;
            if (HILO) {
                const size_t o0 = (size_t)row * 3072 + seg * 1024 + cseg;
                const size_t o1 = o0 + (size_t)8 * 3072;
                uint32_t hw, lw;
                split2(v0, v1, hw, lw);
                *reinterpret_cast<uint32_t*>(Chi + o0) = hw;
                *reinterpret_cast<uint32_t*>(Clo + o0) = lw;
                split2(v2, v3, hw, lw);
                *reinterpret_cast<uint32_t*>(Chi + o1) = hw;
                *reinterpret_cast<uint32_t*>(Clo + o1) = lw;
            } else {
                const size_t g0o = (size_t)row * Dv + cseg;
                const size_t g1o = g0o + (size_t)8 * Dv;
                float2 r0 = *reinterpret_cast<const float2*>(res + g0o);
                float2 r1 = *reinterpret_cast<const float2*>(res + g1o);
                *reinterpret_cast<float2*>(Cf + g0o) = make_float2(v0 + r0.x, v1 + r0.y);
                *reinterpret_cast<float2*>(Cf + g1o) = make_float2(v2 + r1.x, v3 + r1.y);
            }
        }
    }
}

// ---------------------------------------------------------------------------
// Tensor-core flash attention.
// grid (T/128, H, B), 256 threads (8 warps x 16 queries).
// K/V hi/lo 64-key tiles double-buffered via cp.async (SW128 swizzle).
// S = QK^T via 3-pass bf16-split mma (fp32-accurate scores), fp32 softmax,
// P split hi/lo in-register, PV via 3-pass mma with ldmatrix.trans on V.
// ---------------------------------------------------------------------------
constexpr int AST = 32768;                   // Khi|Klo|Vhi|Vlo tiles (8KB each)
constexpr int ASMEM = 2 * AST + 1024;

__global__ void __launch_bounds__(256) attn_tc_kernel(
    const __nv_bfloat16* __restrict__ QKVhi, const __nv_bfloat16* __restrict__ QKVlo,
    const unsigned* __restrict__ mbits,
    __nv_bfloat16* __restrict__ Yhi, __nv_bfloat16* __restrict__ Ylo)
{
    extern __shared__ char dyns[];
    const uint32_t sraw = smem_to_u32(dyns);
    const uint32_t s0a = (sraw + 1023) & ~1023u;

    const int tid = threadIdx.x, l = tid & 31, w = tid >> 5;
    const int b = blockIdx.z, h = blockIdx.y;
    const int qb = blockIdx.x * 128;
    const int rowb = b * Tv;
    const int qcol = h * 64, kcol = 1024 + h * 64, vcol = 2048 + h * 64;

    // Q fragments (q pre-scaled by 0.125 in QKV epilogue)
    uint32_t qh[4][4], ql[4][4];
    const int r = l >> 2;
    const int row0 = qb + w * 16 + r;       // in-batch query row (lanes share per l>>2)
    {
        const size_t a0 = (size_t)(rowb + row0) * 3072 + qcol;
        const size_t a1 = a0 + (size_t)8 * 3072;
        #pragma unroll
        for (int ks = 0; ks < 4; ks++) {
            const int c0 = ks * 16 + (l & 3) * 2;
            qh[ks][0] = *reinterpret_cast<const uint32_t*>(QKVhi + a0 + c0);
            qh[ks][1] = *reinterpret_cast<const uint32_t*>(QKVhi + a1 + c0);
            qh[ks][2] = *reinterpret_cast<const uint32_t*>(QKVhi + a0 + c0 + 8);
            qh[ks][3] = *reinterpret_cast<const uint32_t*>(QKVhi + a1 + c0 + 8);
            ql[ks][0] = *reinterpret_cast<const uint32_t*>(QKVlo + a0 + c0);
            ql[ks][1] = *reinterpret_cast<const uint32_t*>(QKVlo + a1 + c0);
            ql[ks][2] = *reinterpret_cast<const uint32_t*>(QKVlo + a0 + c0 + 8);
            ql[ks][3] = *reinterpret_cast<const uint32_t*>(QKVlo + a1 + c0 + 8);
        }
    }

    float O[8][4];
    #pragma unroll
    for (int t = 0; t < 8; t++)
        #pragma unroll
        for (int i = 0; i < 4; i++) O[t][i] = 0.0f;
    float m0 = -CUDART_INF_F, m1 = -CUDART_INF_F, l0 = 0.0f, l1 = 0.0f;

    const unsigned* mr0 = mbits + (size_t)(rowb + row0) * (Tv / 32);
    const unsigned* mr1 = mr0 + (size_t)8 * (Tv / 32);

    auto issue = [&](int kt, int st) {
        const uint32_t sb = s0a + st * AST;
        #pragma unroll
        for (int i = 0; i < 2; i++) {
            const int vv = tid + 256 * i;            // 0..511
            const int rr = vv >> 3, c16 = vv & 7;
            const uint32_t sw = SMEM_SWIZZLE_128B((uint32_t)(rr * 128 + c16 * 16));
            const size_t gk = (size_t)(rowb + kt + rr) * 3072 + kcol + c16 * 8;
            const size_t gv = (size_t)(rowb + kt + rr) * 3072 + vcol + c16 * 8;
            CP_ASYNC16(sb + sw,          (const void*)(QKVhi + gk));
            CP_ASYNC16(sb + 8192 + sw,   (const void*)(QKVlo + gk));
            CP_ASYNC16(sb + 16384 + sw,  (const void*)(QKVhi + gv));
            CP_ASYNC16(sb + 24576 + sw,  (const void*)(QKVlo + gv));
        }
    };

    issue(0, 0); CP_COMMIT();

    #pragma unroll 1
    for (int kt = 0; kt < Tv; kt += 64) {
        const int st = (kt >> 6) & 1;
        if (kt + 64 < Tv) { issue(kt + 64, st ^ 1); CP_COMMIT(); CP_WAIT(1); }
        else              { CP_WAIT(0); }
        __syncthreads();

        const uint32_t kb = s0a + st * AST;
        const uint32_t vb = kb + 16384;

        // ---- S = Q K^T (3-pass split) ----
        float S[8][4];
        #pragma unroll
        for (int t = 0; t < 8; t++)
            #pragma unroll
            for (int i = 0; i < 4; i++) S[t][i] = 0.0f;

        #pragma unroll
        for (int ks = 0; ks < 4; ks++) {
            uint32_t bh[8][2], bl[8][2];
            #pragma unroll
            for (int j = 0; j < 4; j++) {
                const int nr = j * 16 + (l & 7) + ((l >> 4) & 1) * 8;
                const uint32_t off = SMEM_SWIZZLE_128B(
                    (uint32_t)(nr * 128 + ks * 32 + ((l >> 3) & 1) * 16));
                uint32_t r0, r1, r2, r3;
                ldsm4(kb + off, r0, r1, r2, r3);
                bh[2*j][0] = r0; bh[2*j][1] = r1; bh[2*j+1][0] = r2; bh[2*j+1][1] = r3;
                ldsm4(kb + 8192 + off, r0, r1, r2, r3);
                bl[2*j][0] = r0; bl[2*j][1] = r1; bl[2*j+1][0] = r2; bl[2*j+1][1] = r3;
            }
            #pragma unroll
            for (int t = 0; t < 8; t++) {
                mma16816(S[t], qh[ks], bh[t]);
                mma16816(S[t], qh[ks], bl[t]);
                mma16816(S[t], ql[ks], bh[t]);
            }
        }

        // ---- mask ----
        const int kw = kt >> 5;
        const unsigned w00 = mr0[kw], w01 = mr0[kw + 1];
        const unsigned w10 = mr1[kw], w11 = mr1[kw + 1];
        #pragma unroll
        for (int t = 0; t < 8; t++) {
            const int c = (t & 3) * 8 + (l & 3) * 2;    // bit within word
            const unsigned wa = (t < 4) ? w00 : w01;
            const unsigned wb = (t < 4) ? w10 : w11;
            if (!((wa >> c) & 1u))       S[t][0] -= 100000.0f;
            if (!((wa >> (c + 1)) & 1u)) S[t][1] -= 100000.0f;
            if (!((wb >> c) & 1u))       S[t][2] -= 100000.0f;
            if (!((wb >> (c + 1)) & 1u)) S[t][3] -= 100000.0f;
        }

        // ---- online softmax ----
        float mx0 = -CUDART_INF_F, mx1 = -CUDART_INF_F;
        #pragma unroll
        for (int t = 0; t < 8; t++) {
            mx0 = fmaxf(mx0, fmaxf(S[t][0], S[t][1]));
            mx1 = fmaxf(mx1, fmaxf(S[t][2], S[t][3]));
        }
        mx0 = fmaxf(mx0, __shfl_xor_sync(0xffffffffu, mx0, 1));
        mx0 = fmaxf(mx0, __shfl_xor_sync(0xffffffffu, mx0, 2));
        mx1 = fmaxf(mx1, __shfl_xor_sync(0xffffffffu, mx1, 1));
        mx1 = fmaxf(mx1, __shfl_xor_sync(0xffffffffu, mx1, 2));

        const float mn0 = fmaxf(m0, mx0), mn1 = fmaxf(m1, mx1);
        const float sc0 = __expf(m0 - mn0), sc1 = __expf(m1 - mn1);
        m0 = mn0; m1 = mn1;
        l0 *= sc0; l1 *= sc1;

        #pragma unroll
        for (int t = 0; t < 8; t++) {
            S[t][0] = __expf(S[t][0] - m0);
            S[t][1] = __expf(S[t][1] - m0);
            S[t][2] = __expf(S[t][2] - m1);
            S[t][3] = __expf(S[t][3] - m1);
            l0 += S[t][0] + S[t][1];
            l1 += S[t][2] + S[t][3];
            O[t][0] *= sc0; O[t][1] *= sc0; O[t][2] *= sc1; O[t][3] *= sc1;
        }

        // ---- O += P V (3-pass split; V via ldmatrix.trans) ----
        #pragma unroll
        for (int ks = 0; ks < 4; ks++) {
            uint32_t ph[4], pl[4];
            split2(S[2*ks][0],   S[2*ks][1],   ph[0], pl[0]);
            split2(S[2*ks][2],   S[2*ks][3],   ph[1], pl[1]);
            split2(S[2*ks+1][0], S[2*ks+1][1], ph[2], pl[2]);
            split2(S[2*ks+1][2], S[2*ks+1][3], ph[3], pl[3]);

            uint32_t vh[8][2], vl[8][2];
            const int vr = ks * 16 + (l & 7) + ((l >> 3) & 1) * 8;
            #pragma unroll
            for (int j = 0; j < 4; j++) {
                const uint32_t off = SMEM_SWIZZLE_128B(
                    (uint32_t)(vr * 128 + (j * 16 + ((l >> 4) & 1) * 8) * 2));
                uint32_t r0, r1, r2, r3;
                ldsm4t(vb + off, r0, r1, r2, r3);
                vh[2*j][0] = r0; vh[2*j][1] = r1; vh[2*j+1][0] = r2; vh[2*j+1][1] = r3;
                ldsm4t(vb + 8192 + off, r0, r1, r2, r3);
                vl[2*j][0] = r0; vl[2*j][1] = r1; vl[2*j+1][0] = r2; vl[2*j+1][1] = r3;
            }
            #pragma unroll
            for (int t = 0; t < 8; t++) {
                mma16816(O[t], ph, vh[t]);
                mma16816(O[t], ph, vl[t]);
                mma16816(O[t], pl, vh[t]);
            }
        }
        __syncthreads();
    }

    // ---- finalize: normalize and emit y hi/lo ----
    l0 += __shfl_xor_sync(0xffffffffu, l0, 1);
    l0 += __shfl_xor_sync(0xffffffffu, l0, 2);
    l1 += __shfl_xor_sync(0xffffffffu, l1, 1);
    l1 += __shfl_xor_sync(0xffffffffu, l1, 2);
    const float inv0 = 1.0f / l0, inv1 = 1.0f / l1;

    const size_t y0 = (size_t)(rowb + row0) * Dv + h * 64;
    const size_t y1 = y0 + (size_t)8 * Dv;
    #pragma unroll
    for (int t = 0; t < 8; t++) {
        const int col = t * 8 + (l & 3) * 2;
        uint32_t hw, lw;
        split2(O[t][0] * inv0, O[t][1] * inv0, hw, lw);
        *reinterpret_cast<uint32_t*>(Yhi + y0 + col) = hw;
        *reinterpret_cast<uint32_t*>(Ylo + y0 + col) = lw;
        split2(O[t][2] * inv1, O[t][3] * inv1, hw, lw);
        *reinterpret_cast<uint32_t*>(Yhi + y1 + col) = hw;
        *reinterpret_cast<uint32_t*>(Ylo + y1 + col) = lw;
    }
}

// ---------------------------------------------------------------------------
extern "C" void kernel_launch(void* const* d_in, const int* in_sizes, int n_in,
                              void* d_out, int out_size)
{
    const float* x        = (const float*)d_in[0];
    const int*   src_mask = (const int*)  d_in[1];
    const float* ln_gamma = (const float*)d_in[2];
    const float* ln_beta  = (const float*)d_in[3];
    const float* Wq = (const float*)d_in[4];
    const float* bq = (const float*)d_in[5];
    const float* Wk = (const float*)d_in[6];
    const float* bk = (const float*)d_in[7];
    const float* Wv = (const float*)d_in[8];
    const float* bv = (const float*)d_in[9];
    const float* Wo = (const float*)d_in[10];
    const float* bo = (const float*)d_in[11];
    float* out = (float*)d_out;

    __nv_bfloat16 *xnhi, *xnlo, *yhi, *ylo, *qkvhi, *qkvlo;
    unsigned* mbits;
    cudaGetSymbolAddress((void**)&xnhi,  g_xnhi);
    cudaGetSymbolAddress((void**)&xnlo,  g_xnlo);
    cudaGetSymbolAddress((void**)&yhi,   g_yhi);
    cudaGetSymbolAddress((void**)&ylo,   g_ylo);
    cudaGetSymbolAddress((void**)&qkvhi, g_qkvhi);
    cudaGetSymbolAddress((void**)&qkvlo, g_qkvlo);
    cudaGetSymbolAddress((void**)&mbits, g_mbits);

    cudaFuncSetAttribute(gemm_tc_kernel<true>,  cudaFuncAttributeMaxDynamicSharedMemorySize, SMEM_DYN);
    cudaFuncSetAttribute(gemm_tc_kernel<false>, cudaFuncAttributeMaxDynamicSharedMemorySize, SMEM_DYN);
    cudaFuncSetAttribute(attn_tc_kernel,        cudaFuncAttributeMaxDynamicSharedMemorySize, ASMEM);

    // 1. pack mask bits
    pack_mask_kernel<<<NWORDS / 8, 256>>>(src_mask, mbits);

    // 2. LayerNorm -> bf16 hi/lo
    ln_kernel<<<MROWS, 128>>>(x, ln_gamma, ln_beta, xnhi, xnlo);

    // 3. weight transpose + hi/lo conversion (Wq, Wk, Wv, Wo)
    wconv_kernel<<<dim3(Dv / 32, Dv / 32, 4), 256>>>(Wq, Wk, Wv, Wo);

    // 4. fused QKV projection -> bf16 hi/lo (q pre-scaled by 0.125)
    gemm_tc_kernel<true><<<dim3(24, 32), 256, SMEM_DYN>>>(
        xnhi, xnlo, 0, nullptr, nullptr, qkvhi, qkvlo, bq, bk, bv);

    // 5. tensor-core masked flash attention (emits y hi/lo)
    attn_tc_kernel<<<dim3(Tv / 128, Hv, Bv), 256, ASMEM>>>(qkvhi, qkvlo, mbits, yhi, ylo);

    // 6. output projection + bias + residual (fp32 out)
    gemm_tc_kernel<false><<<dim3(8, 32), 256, SMEM_DYN>>>(
        yhi, ylo, 3072, out, x, nullptr, nullptr, bo, bo, bo);
}

// round 9
// speedup vs baseline: 3.8469x; 1.1397x over previous
#include <cuda_runtime.h>
#include <cuda_bf16.h>
#include <math_constants.h>
#include <cstdint>

#define Bv 2
#define Tv 2048
#define Dv 1024
#define Hv 16
#define DHv 64
constexpr int MROWS = Bv * Tv;               // 4096
constexpr int NWORDS = Bv * Tv * (Tv / 32);  // 262144

// ---------------- scratch (__device__ globals; no allocation allowed) -------
__device__ __nv_bfloat16 g_xnhi[MROWS * Dv];
__device__ __nv_bfloat16 g_xnlo[MROWS * Dv];
__device__ __nv_bfloat16 g_wthi[4 * Dv * Dv];   // [Wq^T; Wk^T; Wv^T; Wo^T] rows=[n], cols=[k]
__device__ __nv_bfloat16 g_wtlo[4 * Dv * Dv];
__device__ __nv_bfloat16 g_qkvhi[(size_t)MROWS * 3072];  // [row][q|k|v]
__device__ __nv_bfloat16 g_qkvlo[(size_t)MROWS * 3072];
__device__ __nv_bfloat16 g_yhi[MROWS * Dv];
__device__ __nv_bfloat16 g_ylo[MROWS * Dv];
__device__ unsigned g_mbits[NWORDS];

// ---------------- helpers ----------------------------------------------------
__device__ __forceinline__ uint32_t smem_to_u32(const void* p) {
    uint32_t a;
    asm("{ .reg .u64 t; cvta.to.shared.u64 t, %1; cvt.u32.u64 %0, t; }" : "=r"(a) : "l"(p));
    return a;
}

#define SMEM_SWIZZLE_128B(o) ((o) ^ (((o) >> 3) & 0x70))
#define SMEM_SWIZZLE_64B(o)  ((o) ^ (((o) >> 3) & 0x30))

#define CP_ASYNC16(smem_u32, gptr) \
    asm volatile("cp.async.cg.shared.global [%0], [%1], 16;" \
                 :: "r"(smem_u32), "l"(gptr) : "memory")
#define CP_COMMIT() asm volatile("cp.async.commit_group;" ::: "memory")
#define CP_WAIT(n)  asm volatile("cp.async.wait_group %0;" :: "n"(n) : "memory")

__device__ __forceinline__ void ldsm4(uint32_t addr, uint32_t& r0, uint32_t& r1,
                                      uint32_t& r2, uint32_t& r3) {
    asm volatile("ldmatrix.sync.aligned.m8n8.x4.shared.b16 {%0,%1,%2,%3}, [%4];"
                 : "=r"(r0), "=r"(r1), "=r"(r2), "=r"(r3) : "r"(addr));
}
__device__ __forceinline__ void ldsm4t(uint32_t addr, uint32_t& r0, uint32_t& r1,
                                       uint32_t& r2, uint32_t& r3) {
    asm volatile("ldmatrix.sync.aligned.m8n8.x4.trans.shared.b16 {%0,%1,%2,%3}, [%4];"
                 : "=r"(r0), "=r"(r1), "=r"(r2), "=r"(r3) : "r"(addr));
}

__device__ __forceinline__ void mma16816(float* c, const uint32_t* a, const uint32_t* b) {
    asm volatile(
        "mma.sync.aligned.m16n8k16.row.col.f32.bf16.bf16.f32 "
        "{%0,%1,%2,%3}, {%4,%5,%6,%7}, {%8,%9}, {%0,%1,%2,%3};"
        : "+f"(c[0]), "+f"(c[1]), "+f"(c[2]), "+f"(c[3])
        : "r"(a[0]), "r"(a[1]), "r"(a[2]), "r"(a[3]), "r"(b[0]), "r"(b[1]));
}

// split a float pair into packed bf16 hi + bf16 lo (residual) words
__device__ __forceinline__ void split2(float a, float b, uint32_t& hi, uint32_t& lo) {
    __nv_bfloat162 h = __floats2bfloat162_rn(a, b);
    float la = a - __bfloat162float(h.x);
    float lb = b - __bfloat162float(h.y);
    __nv_bfloat162 l2 = __floats2bfloat162_rn(la, lb);
    hi = *reinterpret_cast<uint32_t*>(&h);
    lo = *reinterpret_cast<uint32_t*>(&l2);
}

__device__ __forceinline__ void store_hilo4(__nv_bfloat16* Hi, __nv_bfloat16* Lo,
                                            size_t idx, float4 o) {
    uint32_t h0, l0, h1, l1;
    split2(o.x, o.y, h0, l0);
    split2(o.z, o.w, h1, l1);
    uint2 hv = make_uint2(h0, h1), lv = make_uint2(l0, l1);
    *reinterpret_cast<uint2*>(Hi + idx) = hv;
    *reinterpret_cast<uint2*>(Lo + idx) = lv;
}

// ---------------------------------------------------------------------------
// Pack src_mask into bitmask words (bit set = attend)
// ---------------------------------------------------------------------------
__global__ void __launch_bounds__(256) pack_mask_kernel(const int* __restrict__ mask,
                                                        unsigned* __restrict__ bits)
{
    int w = blockIdx.x * (blockDim.x >> 5) + (threadIdx.x >> 5);
    int lane = threadIdx.x & 31;
    int v = mask[(size_t)w * 32 + lane];
    unsigned b = __ballot_sync(0xffffffffu, v != 0);
    if (lane == 0) bits[w] = b;
}

// ---------------------------------------------------------------------------
// LayerNorm -> bf16 hi/lo split output
// ---------------------------------------------------------------------------
__global__ void __launch_bounds__(128) ln_kernel(const float* __restrict__ x,
                                                 const float* __restrict__ gamma,
                                                 const float* __restrict__ beta,
                                                 __nv_bfloat16* __restrict__ ohi,
                                                 __nv_bfloat16* __restrict__ olo)
{
    const int row = blockIdx.x;
    const int t = threadIdx.x;
    const float4* xr = reinterpret_cast<const float4*>(x + (size_t)row * Dv);
    float4 v0 = xr[t], v1 = xr[t + 128];

    float s  = v0.x + v0.y + v0.z + v0.w + v1.x + v1.y + v1.z + v1.w;
    float ss = v0.x*v0.x + v0.y*v0.y + v0.z*v0.z + v0.w*v0.w
             + v1.x*v1.x + v1.y*v1.y + v1.z*v1.z + v1.w*v1.w;

    #pragma unroll
    for (int off = 16; off > 0; off >>= 1) {
        s  += __shfl_xor_sync(0xffffffffu, s,  off);
        ss += __shfl_xor_sync(0xffffffffu, ss, off);
    }
    __shared__ float red[8];
    int warp = t >> 5, lane = t & 31;
    if (lane == 0) { red[warp] = s; red[warp + 4] = ss; }
    __syncthreads();
    s  = red[0] + red[1] + red[2] + red[3];
    ss = red[4] + red[5] + red[6] + red[7];

    const float mean = s * (1.0f / Dv);
    const float var  = ss * (1.0f / Dv) - mean * mean;
    const float rstd = rsqrtf(var + 1e-5f);

    const float4* g4 = reinterpret_cast<const float4*>(gamma);
    const float4* b4 = reinterpret_cast<const float4*>(beta);
    float4 g0 = g4[t], g1 = g4[t + 128];
    float4 e0 = b4[t], e1 = b4[t + 128];
    float4 o;
    o.x = (v0.x - mean) * rstd * g0.x + e0.x;
    o.y = (v0.y - mean) * rstd * g0.y + e0.y;
    o.z = (v0.z - mean) * rstd * g0.z + e0.z;
    o.w = (v0.w - mean) * rstd * g0.w + e0.w;
    store_hilo4(ohi, olo, (size_t)row * Dv + t * 4, o);
    o.x = (v1.x - mean) * rstd * g1.x + e1.x;
    o.y = (v1.y - mean) * rstd * g1.y + e1.y;
    o.z = (v1.z - mean) * rstd * g1.z + e1.z;
    o.w = (v1.w - mean) * rstd * g1.w + e1.w;
    store_hilo4(ohi, olo, (size_t)row * Dv + (t + 128) * 4, o);
}

// ---------------------------------------------------------------------------
// Weight transpose + bf16 hi/lo conversion: g_wt[z*1024 + n][k] = W_z[k][n]
// ---------------------------------------------------------------------------
__global__ void __launch_bounds__(256) wconv_kernel(const float* __restrict__ w0,
                                                    const float* __restrict__ w1,
                                                    const float* __restrict__ w2,
                                                    const float* __restrict__ w3)
{
    __shared__ float tile[32][33];
    const float* src = (blockIdx.z == 0) ? w0 : (blockIdx.z == 1) ? w1
                     : (blockIdx.z == 2) ? w2 : w3;
    int kt = blockIdx.x * 32, nt = blockIdx.y * 32;
    int tx = threadIdx.x & 31, ty = threadIdx.x >> 5;
    #pragma unroll
    for (int i = 0; i < 4; i++)
        tile[ty + 8 * i][tx] = src[(size_t)(kt + ty + 8 * i) * Dv + nt + tx];
    __syncthreads();
    size_t off = (size_t)blockIdx.z * Dv;
    #pragma unroll
    for (int i = 0; i < 4; i++) {
        int n = nt + ty + 8 * i, kk = kt + tx;
        float v = tile[tx][ty + 8 * i];
        __nv_bfloat16 hi = __float2bfloat16(v);
        float lof = v - __bfloat162float(hi);
        g_wthi[(off + n) * Dv + kk] = hi;
        g_wtlo[(off + n) * Dv + kk] = __float2bfloat16(lof);
    }
}

// ---------------------------------------------------------------------------
// mma.sync bf16-split GEMM. CTA tile 128x128, 8 warps (2x4), K-chunk 32,
// 3-stage cp.async pipeline, SW64-swizzled smem (64B rows), 2 CTAs/SM.
//   C = Ahi@Bhi^T + Ahi@Blo^T + Alo@Bhi^T   (fp32 accum)
// ---------------------------------------------------------------------------
constexpr int GTILE = 8192;                  // one 128x32 bf16 tile
constexpr int STAGE = 4 * GTILE;             // Ahi|Alo|Whi|Wlo (32KB)
constexpr int NSTG = 3;
constexpr int SMEM_DYN = NSTG * STAGE + 1024;

template <bool HILO>
__global__ void __launch_bounds__(256, 2) gemm_tc_kernel(
    const __nv_bfloat16* __restrict__ Ahi, const __nv_bfloat16* __restrict__ Alo,
    int wrow_off,
    float* Cf, const float* res,
    __nv_bfloat16* Chi, __nv_bfloat16* Clo,
    const float* b0, const float* b1, const float* b2)
{
    extern __shared__ char dyns[];
    const uint32_t sraw = smem_to_u32(dyns);
    const uint32_t s0 = (sraw + 1023) & ~1023u;

    const int tid = threadIdx.x;
    const int bm = blockIdx.y * 128;
    const int bx = blockIdx.x;
    const int wrow = wrow_off + bx * 128;

    float acc[4][4][4];
    #pragma unroll
    for (int i = 0; i < 4; i++)
        #pragma unroll
        for (int j = 0; j < 4; j++)
            #pragma unroll
            for (int r = 0; r < 4; r++) acc[i][j][r] = 0.0f;

    // loaders: 512 16B-vectors per 128x32 tile; each thread does 2
    const int lr  = tid >> 2;            // row 0..63 (then +64)
    const int lc8 = (tid & 3) * 8;       // bf16 col
    const uint32_t lcb = (tid & 3) * 16; // byte col

    auto issue_loads = [&](int c, int st) {
        const uint32_t sb = s0 + st * STAGE;
        #pragma unroll
        for (int i = 0; i < 2; i++) {
            const int r = lr + 64 * i;
            const uint32_t sw = SMEM_SWIZZLE_64B((uint32_t)(r * 64) + lcb);
            const size_t ga = (size_t)(bm + r) * Dv + c * 32 + lc8;
            const size_t gw = (size_t)(wrow + r) * Dv + c * 32 + lc8;
            CP_ASYNC16(sb + sw,             (const void*)(Ahi + ga));
            CP_ASYNC16(sb + GTILE + sw,     (const void*)(Alo + ga));
            CP_ASYNC16(sb + 2 * GTILE + sw, (const void*)(g_wthi + gw));
            CP_ASYNC16(sb + 3 * GTILE + sw, (const void*)(g_wtlo + gw));
        }
    };

    const int l = tid & 31;
    const int w = tid >> 5;
    const int wm = (w >> 2) * 64;
    const int wn = (w & 3) * 32;

    auto compute = [&](int st) {
        const uint32_t sb = s0 + st * STAGE;
        #pragma unroll
        for (int ks = 0; ks < 2; ks++) {
            uint32_t bh[4][2], bl[4][2];
            const int bkb = ks * 32 + ((l >> 3) & 1) * 16;
            #pragma unroll
            for (int j = 0; j < 2; j++) {
                const int nr = wn + j * 16 + (l & 7) + ((l >> 4) & 1) * 8;
                const uint32_t off = SMEM_SWIZZLE_64B((uint32_t)(nr * 64 + bkb));
                uint32_t r0, r1, r2, r3;
                ldsm4(sb + 2 * GTILE + off, r0, r1, r2, r3);
                bh[2 * j][0] = r0; bh[2 * j][1] = r1;
                bh[2 * j + 1][0] = r2; bh[2 * j + 1][1] = r3;
                ldsm4(sb + 3 * GTILE + off, r0, r1, r2, r3);
                bl[2 * j][0] = r0; bl[2 * j][1] = r1;
                bl[2 * j + 1][0] = r2; bl[2 * j + 1][1] = r3;
            }
            const int akb = ks * 32 + ((l >> 4) & 1) * 16;
            #pragma unroll
            for (int mt = 0; mt < 4; mt++) {
                uint32_t ah[4], al[4];
                const int row = wm + mt * 16 + (l & 7) + ((l >> 3) & 1) * 8;
                const uint32_t off = SMEM_SWIZZLE_64B((uint32_t)(row * 64 + akb));
                ldsm4(sb + off,         ah[0], ah[1], ah[2], ah[3]);
                ldsm4(sb + GTILE + off, al[0], al[1], al[2], al[3]);
                #pragma unroll
                for (int nt = 0; nt < 4; nt++) {
                    mma16816(acc[mt][nt], ah, bh[nt]);
                    mma16816(acc[mt][nt], ah, bl[nt]);
                    mma16816(acc[mt][nt], al, bh[nt]);
                }
            }
        }
    };

    issue_loads(0, 0); CP_COMMIT();
    issue_loads(1, 1); CP_COMMIT();
    #pragma unroll 1
    for (int c = 0; c < 32; c++) {
        if (c + 2 < 32) { issue_loads(c + 2, (c + 2) % NSTG); CP_COMMIT(); CP_WAIT(2); }
        else if (c + 1 < 32) { CP_WAIT(1); }
        else { CP_WAIT(0); }
        __syncthreads();
        compute(c % NSTG);
        __syncthreads();
    }

    // ---- epilogue ----
    const int seg = bx >> 3;
    const float* bias = (seg == 0) ? b0 : (seg == 1) ? b1 : b2;
    const float scale = (HILO && seg == 0) ? 0.125f : 1.0f;

    #pragma unroll
    for (int mt = 0; mt < 4; mt++) {
        #pragma unroll
        for (int nt = 0; nt < 4; nt++) {
            const int row = bm + wm + mt * 16 + (l >> 2);
            const int cseg = (bx & 7) * 128 + wn + nt * 8 + (l & 3) * 2;  // col within segment
            float2 bb = *reinterpret_cast<const float2*>(bias + cseg);
            float v0 = (acc[mt][nt][0] + bb.x) * scale;
            float v1 = (acc[mt][nt][1] + bb.y) * scale;
            float v2 = (acc[mt][nt][2] + bb.x) * scale;
            float v3 = (acc[mt][nt][3] + bb.y) * scale;
            if (HILO) {
                const size_t o0 = (size_t)row * 3072 + seg * 1024 + cseg;
                const size_t o1 = o0 + (size_t)8 * 3072;
                uint32_t hw, lw;
                split2(v0, v1, hw, lw);
                *reinterpret_cast<uint32_t*>(Chi + o0) = hw;
                *reinterpret_cast<uint32_t*>(Clo + o0) = lw;
                split2(v2, v3, hw, lw);
                *reinterpret_cast<uint32_t*>(Chi + o1) = hw;
                *reinterpret_cast<uint32_t*>(Clo + o1) = lw;
            } else {
                const size_t g0o = (size_t)row * Dv + cseg;
                const size_t g1o = g0o + (size_t)8 * Dv;
                float2 r0 = *reinterpret_cast<const float2*>(res + g0o);
                float2 r1 = *reinterpret_cast<const float2*>(res + g1o);
                *reinterpret_cast<float2*>(Cf + g0o) = make_float2(v0 + r0.x, v1 + r0.y);
                *reinterpret_cast<float2*>(Cf + g1o) = make_float2(v2 + r1.x, v3 + r1.y);
            }
        }
    }
}

// ---------------------------------------------------------------------------
// Tensor-core flash attention.
// grid (T/64, H, B), 128 threads (4 warps x 16 queries = 64 queries/CTA).
// 2-3 CTAs/SM co-resident: one CTA's softmax overlaps another's MMA.
// K/V hi/lo 64-key tiles double-buffered via cp.async (SW128 swizzle).
// ---------------------------------------------------------------------------
constexpr int AST = 32768;                   // Khi|Klo|Vhi|Vlo tiles (8KB each)
constexpr int ASMEM = 2 * AST + 1024;

__global__ void __launch_bounds__(128) attn_tc_kernel(
    const __nv_bfloat16* __restrict__ QKVhi, const __nv_bfloat16* __restrict__ QKVlo,
    const unsigned* __restrict__ mbits,
    __nv_bfloat16* __restrict__ Yhi, __nv_bfloat16* __restrict__ Ylo)
{
    extern __shared__ char dyns[];
    const uint32_t sraw = smem_to_u32(dyns);
    const uint32_t s0a = (sraw + 1023) & ~1023u;

    const int tid = threadIdx.x, l = tid & 31, w = tid >> 5;
    const int b = blockIdx.z, h = blockIdx.y;
    const int qb = blockIdx.x * 64;
    const int rowb = b * Tv;
    const int qcol = h * 64, kcol = 1024 + h * 64, vcol = 2048 + h * 64;

    // Q fragments (q pre-scaled by 0.125 in QKV epilogue)
    uint32_t qh[4][4], ql[4][4];
    const int r = l >> 2;
    const int row0 = qb + w * 16 + r;
    {
        const size_t a0 = (size_t)(rowb + row0) * 3072 + qcol;
        const size_t a1 = a0 + (size_t)8 * 3072;
        #pragma unroll
        for (int ks = 0; ks < 4; ks++) {
            const int c0 = ks * 16 + (l & 3) * 2;
            qh[ks][0] = *reinterpret_cast<const uint32_t*>(QKVhi + a0 + c0);
            qh[ks][1] = *reinterpret_cast<const uint32_t*>(QKVhi + a1 + c0);
            qh[ks][2] = *reinterpret_cast<const uint32_t*>(QKVhi + a0 + c0 + 8);
            qh[ks][3] = *reinterpret_cast<const uint32_t*>(QKVhi + a1 + c0 + 8);
            ql[ks][0] = *reinterpret_cast<const uint32_t*>(QKVlo + a0 + c0);
            ql[ks][1] = *reinterpret_cast<const uint32_t*>(QKVlo + a1 + c0);
            ql[ks][2] = *reinterpret_cast<const uint32_t*>(QKVlo + a0 + c0 + 8);
            ql[ks][3] = *reinterpret_cast<const uint32_t*>(QKVlo + a1 + c0 + 8);
        }
    }

    float O[8][4];
    #pragma unroll
    for (int t = 0; t < 8; t++)
        #pragma unroll
        for (int i = 0; i < 4; i++) O[t][i] = 0.0f;
    float m0 = -CUDART_INF_F, m1 = -CUDART_INF_F, l0 = 0.0f, l1 = 0.0f;

    const unsigned* mr0 = mbits + (size_t)(rowb + row0) * (Tv / 32);
    const unsigned* mr1 = mr0 + (size_t)8 * (Tv / 32);

    auto issue = [&](int kt, int st) {
        const uint32_t sb = s0a + st * AST;
        #pragma unroll
        for (int i = 0; i < 4; i++) {
            const int vv = tid + 128 * i;            // 0..511
            const int rr = vv >> 3, c16 = vv & 7;
            const uint32_t sw = SMEM_SWIZZLE_128B((uint32_t)(rr * 128 + c16 * 16));
            const size_t gk = (size_t)(rowb + kt + rr) * 3072 + kcol + c16 * 8;
            const size_t gv = (size_t)(rowb + kt + rr) * 3072 + vcol + c16 * 8;
            CP_ASYNC16(sb + sw,          (const void*)(QKVhi + gk));
            CP_ASYNC16(sb + 8192 + sw,   (const void*)(QKVlo + gk));
            CP_ASYNC16(sb + 16384 + sw,  (const void*)(QKVhi + gv));
            CP_ASYNC16(sb + 24576 + sw,  (const void*)(QKVlo + gv));
        }
    };

    issue(0, 0); CP_COMMIT();

    #pragma unroll 1
    for (int kt = 0; kt < Tv; kt += 64) {
        const int st = (kt >> 6) & 1;
        if (kt + 64 < Tv) { issue(kt + 64, st ^ 1); CP_COMMIT(); CP_WAIT(1); }
        else              { CP_WAIT(0); }
        __syncthreads();

        const uint32_t kb = s0a + st * AST;
        const uint32_t vb = kb + 16384;

        // ---- S = Q K^T (3-pass split) ----
        float S[8][4];
        #pragma unroll
        for (int t = 0; t < 8; t++)
            #pragma unroll
            for (int i = 0; i < 4; i++) S[t][i] = 0.0f;

        #pragma unroll
        for (int ks = 0; ks < 4; ks++) {
            uint32_t bh[8][2], bl[8][2];
            #pragma unroll
            for (int j = 0; j < 4; j++) {
                const int nr = j * 16 + (l & 7) + ((l >> 4) & 1) * 8;
                const uint32_t off = SMEM_SWIZZLE_128B(
                    (uint32_t)(nr * 128 + ks * 32 + ((l >> 3) & 1) * 16));
                uint32_t r0, r1, r2, r3;
                ldsm4(kb + off, r0, r1, r2, r3);
                bh[2*j][0] = r0; bh[2*j][1] = r1; bh[2*j+1][0] = r2; bh[2*j+1][1] = r3;
                ldsm4(kb + 8192 + off, r0, r1, r2, r3);
                bl[2*j][0] = r0; bl[2*j][1] = r1; bl[2*j+1][0] = r2; bl[2*j+1][1] = r3;
            }
            #pragma unroll
            for (int t = 0; t < 8; t++) {
                mma16816(S[t], qh[ks], bh[t]);
                mma16816(S[t], qh[ks], bl[t]);
                mma16816(S[t], ql[ks], bh[t]);
            }
        }

        // ---- mask ----
        const int kw = kt >> 5;
        const unsigned w00 = mr0[kw], w01 = mr0[kw + 1];
        const unsigned w10 = mr1[kw], w11 = mr1[kw + 1];
        #pragma unroll
        for (int t = 0; t < 8; t++) {
            const int c = (t & 3) * 8 + (l & 3) * 2;
            const unsigned wa = (t < 4) ? w00 : w01;
            const unsigned wb = (t < 4) ? w10 : w11;
            if (!((wa >> c) & 1u))       S[t][0] -= 100000.0f;
            if (!((wa >> (c + 1)) & 1u)) S[t][1] -= 100000.0f;
            if (!((wb >> c) & 1u))       S[t][2] -= 100000.0f;
            if (!((wb >> (c + 1)) & 1u)) S[t][3] -= 100000.0f;
        }

        // ---- online softmax ----
        float mx0 = -CUDART_INF_F, mx1 = -CUDART_INF_F;
        #pragma unroll
        for (int t = 0; t < 8; t++) {
            mx0 = fmaxf(mx0, fmaxf(S[t][0], S[t][1]));
            mx1 = fmaxf(mx1, fmaxf(S[t][2], S[t][3]));
        }
        mx0 = fmaxf(mx0, __shfl_xor_sync(0xffffffffu, mx0, 1));
        mx0 = fmaxf(mx0, __shfl_xor_sync(0xffffffffu, mx0, 2));
        mx1 = fmaxf(mx1, __shfl_xor_sync(0xffffffffu, mx1, 1));
        mx1 = fmaxf(mx1, __shfl_xor_sync(0xffffffffu, mx1, 2));

        const float mn0 = fmaxf(m0, mx0), mn1 = fmaxf(m1, mx1);
        const float sc0 = __expf(m0 - mn0), sc1 = __expf(m1 - mn1);
        m0 = mn0; m1 = mn1;
        l0 *= sc0; l1 *= sc1;

        #pragma unroll
        for (int t = 0; t < 8; t++) {
            S[t][0] = __expf(S[t][0] - m0);
            S[t][1] = __expf(S[t][1] - m0);
            S[t][2] = __expf(S[t][2] - m1);
            S[t][3] = __expf(S[t][3] - m1);
            l0 += S[t][0] + S[t][1];
            l1 += S[t][2] + S[t][3];
            O[t][0] *= sc0; O[t][1] *= sc0; O[t][2] *= sc1; O[t][3] *= sc1;
        }

        // ---- O += P V (3-pass split; V via ldmatrix.trans) ----
        #pragma unroll
        for (int ks = 0; ks < 4; ks++) {
            uint32_t ph[4], pl[4];
            split2(S[2*ks][0],   S[2*ks][1],   ph[0], pl[0]);
            split2(S[2*ks][2],   S[2*ks][3],   ph[1], pl[1]);
            split2(S[2*ks+1][0], S[2*ks+1][1], ph[2], pl[2]);
            split2(S[2*ks+1][2], S[2*ks+1][3], ph[3], pl[3]);

            uint32_t vh[8][2], vl[8][2];
            const int vr = ks * 16 + (l & 7) + ((l >> 3) & 1) * 8;
            #pragma unroll
            for (int j = 0; j < 4; j++) {
                const uint32_t off = SMEM_SWIZZLE_128B(
                    (uint32_t)(vr * 128 + (j * 16 + ((l >> 4) & 1) * 8) * 2));
                uint32_t r0, r1, r2, r3;
                ldsm4t(vb + off, r0, r1, r2, r3);
                vh[2*j][0] = r0; vh[2*j][1] = r1; vh[2*j+1][0] = r2; vh[2*j+1][1] = r3;
                ldsm4t(vb + 8192 + off, r0, r1, r2, r3);
                vl[2*j][0] = r0; vl[2*j][1] = r1; vl[2*j+1][0] = r2; vl[2*j+1][1] = r3;
            }
            #pragma unroll
            for (int t = 0; t < 8; t++) {
                mma16816(O[t], ph, vh[t]);
                mma16816(O[t], ph, vl[t]);
                mma16816(O[t], pl, vh[t]);
            }
        }
        __syncthreads();
    }

    // ---- finalize: normalize and emit y hi/lo ----
    l0 += __shfl_xor_sync(0xffffffffu, l0, 1);
    l0 += __shfl_xor_sync(0xffffffffu, l0, 2);
    l1 += __shfl_xor_sync(0xffffffffu, l1, 1);
    l1 += __shfl_xor_sync(0xffffffffu, l1, 2);
    const float inv0 = 1.0f / l0, inv1 = 1.0f / l1;

    const size_t y0 = (size_t)(rowb + row0) * Dv + h * 64;
    const size_t y1 = y0 + (size_t)8 * Dv;
    #pragma unroll
    for (int t = 0; t < 8; t++) {
        const int col = t * 8 + (l & 3) * 2;
        uint32_t hw, lw;
        split2(O[t][0] * inv0, O[t][1] * inv0, hw, lw);
        *reinterpret_cast<uint32_t*>(Yhi + y0 + col) = hw;
        *reinterpret_cast<uint32_t*>(Ylo + y0 + col) = lw;
        split2(O[t][2] * inv1, O[t][3] * inv1, hw, lw);
        *reinterpret_cast<uint32_t*>(Yhi + y1 + col) = hw;
        *reinterpret_cast<uint32_t*>(Ylo + y1 + col) = lw;
    }
}

// ---------------------------------------------------------------------------
extern "C" void kernel_launch(void* const* d_in, const int* in_sizes, int n_in,
                              void* d_out, int out_size)
{
    const float* x        = (const float*)d_in[0];
    const int*   src_mask = (const int*)  d_in[1];
    const float* ln_gamma = (const float*)d_in[2];
    const float* ln_beta  = (const float*)d_in[3];
    const float* Wq = (const float*)d_in[4];
    const float* bq = (const float*)d_in[5];
    const float* Wk = (const float*)d_in[6];
    const float* bk = (const float*)d_in[7];
    const float* Wv = (const float*)d_in[8];
    const float* bv = (const float*)d_in[9];
    const float* Wo = (const float*)d_in[10];
    const float* bo = (const float*)d_in[11];
    float* out = (float*)d_out;

    __nv_bfloat16 *xnhi, *xnlo, *yhi, *ylo, *qkvhi, *qkvlo;
    unsigned* mbits;
    cudaGetSymbolAddress((void**)&xnhi,  g_xnhi);
    cudaGetSymbolAddress((void**)&xnlo,  g_xnlo);
    cudaGetSymbolAddress((void**)&yhi,   g_yhi);
    cudaGetSymbolAddress((void**)&ylo,   g_ylo);
    cudaGetSymbolAddress((void**)&qkvhi, g_qkvhi);
    cudaGetSymbolAddress((void**)&qkvlo, g_qkvlo);
    cudaGetSymbolAddress((void**)&mbits, g_mbits);

    cudaFuncSetAttribute(gemm_tc_kernel<true>,  cudaFuncAttributeMaxDynamicSharedMemorySize, SMEM_DYN);
    cudaFuncSetAttribute(gemm_tc_kernel<false>, cudaFuncAttributeMaxDynamicSharedMemorySize, SMEM_DYN);
    cudaFuncSetAttribute(attn_tc_kernel,        cudaFuncAttributeMaxDynamicSharedMemorySize, ASMEM);

    // 1. pack mask bits
    pack_mask_kernel<<<NWORDS / 8, 256>>>(src_mask, mbits);

    // 2. LayerNorm -> bf16 hi/lo
    ln_kernel<<<MROWS, 128>>>(x, ln_gamma, ln_beta, xnhi, xnlo);

    // 3. weight transpose + hi/lo conversion (Wq, Wk, Wv, Wo)
    wconv_kernel<<<dim3(Dv / 32, Dv / 32, 4), 256>>>(Wq, Wk, Wv, Wo);

    // 4. fused QKV projection -> bf16 hi/lo (q pre-scaled by 0.125)
    gemm_tc_kernel<true><<<dim3(24, 32), 256, SMEM_DYN>>>(
        xnhi, xnlo, 0, nullptr, nullptr, qkvhi, qkvlo, bq, bk, bv);

    // 5. tensor-core masked flash attention (emits y hi/lo)
    attn_tc_kernel<<<dim3(Tv / 64, Hv, Bv), 128, ASMEM>>>(qkvhi, qkvlo, mbits, yhi, ylo);

    // 6. output projection + bias + residual (fp32 out)
    gemm_tc_kernel<false><<<dim3(8, 32), 256, SMEM_DYN>>>(
        yhi, ylo, 3072, out, x, nullptr, nullptr, bo, bo, bo);
}

// round 10
// speedup vs baseline: 3.9353x; 1.0230x over previous
#include <cuda_runtime.h>
#include <cuda_bf16.h>
#include <math_constants.h>
#include <cstdint>

#define Bv 2
#define Tv 2048
#define Dv 1024
#define Hv 16
#define DHv 64
constexpr int MROWS = Bv * Tv;               // 4096
constexpr int NWORDS = Bv * Tv * (Tv / 32);  // 262144

// ---------------- scratch (__device__ globals; no allocation allowed) -------
__device__ __nv_bfloat16 g_xnhi[MROWS * Dv];
__device__ __nv_bfloat16 g_xnlo[MROWS * Dv];
__device__ __nv_bfloat16 g_wthi[4 * Dv * Dv];   // [Wq^T; Wk^T; Wv^T; Wo^T] rows=[n], cols=[k]
__device__ __nv_bfloat16 g_wtlo[4 * Dv * Dv];
__device__ __nv_bfloat16 g_qkvhi[(size_t)MROWS * 3072];  // [row][q|k|v]
__device__ __nv_bfloat16 g_qkvlo[(size_t)MROWS * 3072];
__device__ __nv_bfloat16 g_yhi[MROWS * Dv];
__device__ __nv_bfloat16 g_ylo[MROWS * Dv];
__device__ unsigned g_mbits[NWORDS];

// ---------------- helpers ----------------------------------------------------
__device__ __forceinline__ uint32_t smem_to_u32(const void* p) {
    uint32_t a;
    asm("{ .reg .u64 t; cvta.to.shared.u64 t, %1; cvt.u32.u64 %0, t; }" : "=r"(a) : "l"(p));
    return a;
}

#define SMEM_SWIZZLE_128B(o) ((o) ^ (((o) >> 3) & 0x70))
#define SMEM_SWIZZLE_64B(o)  ((o) ^ (((o) >> 3) & 0x30))

#define CP_ASYNC16(smem_u32, gptr) \
    asm volatile("cp.async.cg.shared.global [%0], [%1], 16;" \
                 :: "r"(smem_u32), "l"(gptr) : "memory")
#define CP_COMMIT() asm volatile("cp.async.commit_group;" ::: "memory")
#define CP_WAIT(n)  asm volatile("cp.async.wait_group %0;" :: "n"(n) : "memory")

__device__ __forceinline__ void ldsm4(uint32_t addr, uint32_t& r0, uint32_t& r1,
                                      uint32_t& r2, uint32_t& r3) {
    asm volatile("ldmatrix.sync.aligned.m8n8.x4.shared.b16 {%0,%1,%2,%3}, [%4];"
                 : "=r"(r0), "=r"(r1), "=r"(r2), "=r"(r3) : "r"(addr));
}
__device__ __forceinline__ void ldsm4t(uint32_t addr, uint32_t& r0, uint32_t& r1,
                                       uint32_t& r2, uint32_t& r3) {
    asm volatile("ldmatrix.sync.aligned.m8n8.x4.trans.shared.b16 {%0,%1,%2,%3}, [%4];"
                 : "=r"(r0), "=r"(r1), "=r"(r2), "=r"(r3) : "r"(addr));
}

__device__ __forceinline__ void mma16816(float* c, const uint32_t* a, const uint32_t* b) {
    asm volatile(
        "mma.sync.aligned.m16n8k16.row.col.f32.bf16.bf16.f32 "
        "{%0,%1,%2,%3}, {%4,%5,%6,%7}, {%8,%9}, {%0,%1,%2,%3};"
        : "+f"(c[0]), "+f"(c[1]), "+f"(c[2]), "+f"(c[3])
        : "r"(a[0]), "r"(a[1]), "r"(a[2]), "r"(a[3]), "r"(b[0]), "r"(b[1]));
}

__device__ __forceinline__ float ex2f(float x) {
    float r;
    asm("ex2.approx.ftz.f32 %0, %1;" : "=f"(r) : "f"(x));
    return r;
}

// split a float pair into packed bf16 hi + bf16 lo (residual) words
__device__ __forceinline__ void split2(float a, float b, uint32_t& hi, uint32_t& lo) {
    __nv_bfloat162 h = __floats2bfloat162_rn(a, b);
    float la = a - __bfloat162float(h.x);
    float lb = b - __bfloat162float(h.y);
    __nv_bfloat162 l2 = __floats2bfloat162_rn(la, lb);
    hi = *reinterpret_cast<uint32_t*>(&h);
    lo = *reinterpret_cast<uint32_t*>(&l2);
}

__device__ __forceinline__ void store_hilo4(__nv_bfloat16* Hi, __nv_bfloat16* Lo,
                                            size_t idx, float4 o) {
    uint32_t h0, l0, h1, l1;
    split2(o.x, o.y, h0, l0);
    split2(o.z, o.w, h1, l1);
    uint2 hv = make_uint2(h0, h1), lv = make_uint2(l0, l1);
    *reinterpret_cast<uint2*>(Hi + idx) = hv;
    *reinterpret_cast<uint2*>(Lo + idx) = lv;
}

// ---------------------------------------------------------------------------
// Pack src_mask into bitmask words (bit set = attend)
// ---------------------------------------------------------------------------
__global__ void __launch_bounds__(256) pack_mask_kernel(const int* __restrict__ mask,
                                                        unsigned* __restrict__ bits)
{
    int w = blockIdx.x * (blockDim.x >> 5) + (threadIdx.x >> 5);
    int lane = threadIdx.x & 31;
    int v = mask[(size_t)w * 32 + lane];
    unsigned b = __ballot_sync(0xffffffffu, v != 0);
    if (lane == 0) bits[w] = b;
}

// ---------------------------------------------------------------------------
// LayerNorm -> bf16 hi/lo split output
// ---------------------------------------------------------------------------
__global__ void __launch_bounds__(128) ln_kernel(const float* __restrict__ x,
                                                 const float* __restrict__ gamma,
                                                 const float* __restrict__ beta,
                                                 __nv_bfloat16* __restrict__ ohi,
                                                 __nv_bfloat16* __restrict__ olo)
{
    const int row = blockIdx.x;
    const int t = threadIdx.x;
    const float4* xr = reinterpret_cast<const float4*>(x + (size_t)row * Dv);
    float4 v0 = xr[t], v1 = xr[t + 128];

    float s  = v0.x + v0.y + v0.z + v0.w + v1.x + v1.y + v1.z + v1.w;
    float ss = v0.x*v0.x + v0.y*v0.y + v0.z*v0.z + v0.w*v0.w
             + v1.x*v1.x + v1.y*v1.y + v1.z*v1.z + v1.w*v1.w;

    #pragma unroll
    for (int off = 16; off > 0; off >>= 1) {
        s  += __shfl_xor_sync(0xffffffffu, s,  off);
        ss += __shfl_xor_sync(0xffffffffu, ss, off);
    }
    __shared__ float red[8];
    int warp = t >> 5, lane = t & 31;
    if (lane == 0) { red[warp] = s; red[warp + 4] = ss; }
    __syncthreads();
    s  = red[0] + red[1] + red[2] + red[3];
    ss = red[4] + red[5] + red[6] + red[7];

    const float mean = s * (1.0f / Dv);
    const float var  = ss * (1.0f / Dv) - mean * mean;
    const float rstd = rsqrtf(var + 1e-5f);

    const float4* g4 = reinterpret_cast<const float4*>(gamma);
    const float4* b4 = reinterpret_cast<const float4*>(beta);
    float4 g0 = g4[t], g1 = g4[t + 128];
    float4 e0 = b4[t], e1 = b4[t + 128];
    float4 o;
    o.x = (v0.x - mean) * rstd * g0.x + e0.x;
    o.y = (v0.y - mean) * rstd * g0.y + e0.y;
    o.z = (v0.z - mean) * rstd * g0.z + e0.z;
    o.w = (v0.w - mean) * rstd * g0.w + e0.w;
    store_hilo4(ohi, olo, (size_t)row * Dv + t * 4, o);
    o.x = (v1.x - mean) * rstd * g1.x + e1.x;
    o.y = (v1.y - mean) * rstd * g1.y + e1.y;
    o.z = (v1.z - mean) * rstd * g1.z + e1.z;
    o.w = (v1.w - mean) * rstd * g1.w + e1.w;
    store_hilo4(ohi, olo, (size_t)row * Dv + (t + 128) * 4, o);
}

// ---------------------------------------------------------------------------
// Weight transpose + bf16 hi/lo conversion: g_wt[z*1024 + n][k] = W_z[k][n]
// ---------------------------------------------------------------------------
__global__ void __launch_bounds__(256) wconv_kernel(const float* __restrict__ w0,
                                                    const float* __restrict__ w1,
                                                    const float* __restrict__ w2,
                                                    const float* __restrict__ w3)
{
    __shared__ float tile[32][33];
    const float* src = (blockIdx.z == 0) ? w0 : (blockIdx.z == 1) ? w1
                     : (blockIdx.z == 2) ? w2 : w3;
    int kt = blockIdx.x * 32, nt = blockIdx.y * 32;
    int tx = threadIdx.x & 31, ty = threadIdx.x >> 5;
    #pragma unroll
    for (int i = 0; i < 4; i++)
        tile[ty + 8 * i][tx] = src[(size_t)(kt + ty + 8 * i) * Dv + nt + tx];
    __syncthreads();
    size_t off = (size_t)blockIdx.z * Dv;
    #pragma unroll
    for (int i = 0; i < 4; i++) {
        int n = nt + ty + 8 * i, kk = kt + tx;
        float v = tile[tx][ty + 8 * i];
        __nv_bfloat16 hi = __float2bfloat16(v);
        float lof = v - __bfloat162float(hi);
        g_wthi[(off + n) * Dv + kk] = hi;
        g_wtlo[(off + n) * Dv + kk] = __float2bfloat16(lof);
    }
}

// ---------------------------------------------------------------------------
// mma.sync bf16-split GEMM. CTA tile 128x128, 8 warps (2x4), K-chunk 32,
// 3-stage cp.async pipeline with ONE barrier per chunk, 2 CTAs/SM.
//   C = Ahi@Bhi^T + Ahi@Blo^T + Alo@Bhi^T   (fp32 accum)
// ---------------------------------------------------------------------------
constexpr int GTILE = 8192;                  // one 128x32 bf16 tile
constexpr int STAGE = 4 * GTILE;             // Ahi|Alo|Whi|Wlo (32KB)
constexpr int NSTG = 3;
constexpr int SMEM_DYN = NSTG * STAGE + 1024;

template <bool HILO>
__global__ void __launch_bounds__(256, 2) gemm_tc_kernel(
    const __nv_bfloat16* __restrict__ Ahi, const __nv_bfloat16* __restrict__ Alo,
    int wrow_off,
    float* Cf, const float* res,
    __nv_bfloat16* Chi, __nv_bfloat16* Clo,
    const float* b0, const float* b1, const float* b2)
{
    extern __shared__ char dyns[];
    const uint32_t sraw = smem_to_u32(dyns);
    const uint32_t s0 = (sraw + 1023) & ~1023u;

    const int tid = threadIdx.x;
    const int bm = blockIdx.y * 128;
    const int bx = blockIdx.x;
    const int wrow = wrow_off + bx * 128;

    float acc[4][4][4];
    #pragma unroll
    for (int i = 0; i < 4; i++)
        #pragma unroll
        for (int j = 0; j < 4; j++)
            #pragma unroll
            for (int r = 0; r < 4; r++) acc[i][j][r] = 0.0f;

    // loaders: 512 16B-vectors per 128x32 tile; each thread does 2
    const int lr  = tid >> 2;            // row 0..63 (then +64)
    const int lc8 = (tid & 3) * 8;       // bf16 col
    const uint32_t lcb = (tid & 3) * 16; // byte col

    auto issue_loads = [&](int c, int st) {
        const uint32_t sb = s0 + st * STAGE;
        #pragma unroll
        for (int i = 0; i < 2; i++) {
            const int r = lr + 64 * i;
            const uint32_t sw = SMEM_SWIZZLE_64B((uint32_t)(r * 64) + lcb);
            const size_t ga = (size_t)(bm + r) * Dv + c * 32 + lc8;
            const size_t gw = (size_t)(wrow + r) * Dv + c * 32 + lc8;
            CP_ASYNC16(sb + sw,             (const void*)(Ahi + ga));
            CP_ASYNC16(sb + GTILE + sw,     (const void*)(Alo + ga));
            CP_ASYNC16(sb + 2 * GTILE + sw, (const void*)(g_wthi + gw));
            CP_ASYNC16(sb + 3 * GTILE + sw, (const void*)(g_wtlo + gw));
        }
    };

    const int l = tid & 31;
    const int w = tid >> 5;
    const int wm = (w >> 2) * 64;
    const int wn = (w & 3) * 32;

    auto compute = [&](int st) {
        const uint32_t sb = s0 + st * STAGE;
        #pragma unroll
        for (int ks = 0; ks < 2; ks++) {
            uint32_t bh[4][2], bl[4][2];
            const int bkb = ks * 32 + ((l >> 3) & 1) * 16;
            #pragma unroll
            for (int j = 0; j < 2; j++) {
                const int nr = wn + j * 16 + (l & 7) + ((l >> 4) & 1) * 8;
                const uint32_t off = SMEM_SWIZZLE_64B((uint32_t)(nr * 64 + bkb));
                uint32_t r0, r1, r2, r3;
                ldsm4(sb + 2 * GTILE + off, r0, r1, r2, r3);
                bh[2 * j][0] = r0; bh[2 * j][1] = r1;
                bh[2 * j + 1][0] = r2; bh[2 * j + 1][1] = r3;
                ldsm4(sb + 3 * GTILE + off, r0, r1, r2, r3);
                bl[2 * j][0] = r0; bl[2 * j][1] = r1;
                bl[2 * j + 1][0] = r2; bl[2 * j + 1][1] = r3;
            }
            const int akb = ks * 32 + ((l >> 4) & 1) * 16;
            #pragma unroll
            for (int mt = 0; mt < 4; mt++) {
                uint32_t ah[4], al[4];
                const int row = wm + mt * 16 + (l & 7) + ((l >> 3) & 1) * 8;
                const uint32_t off = SMEM_SWIZZLE_64B((uint32_t)(row * 64 + akb));
                ldsm4(sb + off,         ah[0], ah[1], ah[2], ah[3]);
                ldsm4(sb + GTILE + off, al[0], al[1], al[2], al[3]);
                #pragma unroll
                for (int nt = 0; nt < 4; nt++) {
                    mma16816(acc[mt][nt], ah, bh[nt]);
                    mma16816(acc[mt][nt], ah, bl[nt]);
                    mma16816(acc[mt][nt], al, bh[nt]);
                }
            }
        }
    };

    issue_loads(0, 0); CP_COMMIT();
    issue_loads(1, 1); CP_COMMIT();
    #pragma unroll 1
    for (int c = 0; c < 32; c++) {
        if (c + 1 < 32) { CP_WAIT(1); } else { CP_WAIT(0); }
        __syncthreads();
        if (c + 2 < 32) { issue_loads(c + 2, (c + 2) % NSTG); CP_COMMIT(); }
        compute(c % NSTG);
    }

    // ---- epilogue ----
    const int seg = bx >> 3;
    const float* bias = (seg == 0) ? b0 : (seg == 1) ? b1 : b2;
    // q is pre-scaled by 1/sqrt(dh) * log2(e) so softmax can use raw ex2
    const float scale = (HILO && seg == 0) ? 0.125f * 1.4426950408889634f : 1.0f;

    #pragma unroll
    for (int mt = 0; mt < 4; mt++) {
        #pragma unroll
        for (int nt = 0; nt < 4; nt++) {
            const int row = bm + wm + mt * 16 + (l >> 2);
            const int cseg = (bx & 7) * 128 + wn + nt * 8 + (l & 3) * 2;  // col within segment
            float2 bb = *reinterpret_cast<const float2*>(bias + cseg);
            float v0 = (acc[mt][nt][0] + bb.x) * scale;
            float v1 = (acc[mt][nt][1] + bb.y) * scale;
            float v2 = (acc[mt][nt][2] + bb.x) * scale;
            float v3 = (acc[mt][nt][3] + bb.y) * scale;
            if (HILO) {
                const size_t o0 = (size_t)row * 3072 + seg * 1024 + cseg;
                const size_t o1 = o0 + (size_t)8 * 3072;
                uint32_t hw, lw;
                split2(v0, v1, hw, lw);
                *reinterpret_cast<uint32_t*>(Chi + o0) = hw;
                *reinterpret_cast<uint32_t*>(Clo + o0) = lw;
                split2(v2, v3, hw, lw);
                *reinterpret_cast<uint32_t*>(Chi + o1) = hw;
                *reinterpret_cast<uint32_t*>(Clo + o1) = lw;
            } else {
                const size_t g0o = (size_t)row * Dv + cseg;
                const size_t g1o = g0o + (size_t)8 * Dv;
                float2 r0 = *reinterpret_cast<const float2*>(res + g0o);
                float2 r1 = *reinterpret_cast<const float2*>(res + g1o);
                *reinterpret_cast<float2*>(Cf + g0o) = make_float2(v0 + r0.x, v1 + r0.y);
                *reinterpret_cast<float2*>(Cf + g1o) = make_float2(v2 + r1.x, v3 + r1.y);
            }
        }
    }
}

// ---------------------------------------------------------------------------
// Tensor-core flash attention (scores in log2 domain; q pre-scaled by
// 0.125*log2e so p = ex2(s - m) exactly equals exp((q.k)/8 - m_nat)).
// grid (T/64, H, B), 128 threads (4 warps x 16 queries = 64 queries/CTA).
// Double-buffered K/V hi/lo tiles; ONE barrier per key-tile.
// ---------------------------------------------------------------------------
constexpr int AST = 32768;                   // Khi|Klo|Vhi|Vlo tiles (8KB each)
constexpr int ASMEM = 2 * AST + 1024;
#define MASK_PEN 144269.50f                  // 100000 * log2(e)

__global__ void __launch_bounds__(128) attn_tc_kernel(
    const __nv_bfloat16* __restrict__ QKVhi, const __nv_bfloat16* __restrict__ QKVlo,
    const unsigned* __restrict__ mbits,
    __nv_bfloat16* __restrict__ Yhi, __nv_bfloat16* __restrict__ Ylo)
{
    extern __shared__ char dyns[];
    const uint32_t sraw = smem_to_u32(dyns);
    const uint32_t s0a = (sraw + 1023) & ~1023u;

    const int tid = threadIdx.x, l = tid & 31, w = tid >> 5;
    const int b = blockIdx.z, h = blockIdx.y;
    const int qb = blockIdx.x * 64;
    const int rowb = b * Tv;
    const int qcol = h * 64, kcol = 1024 + h * 64, vcol = 2048 + h * 64;

    // Q fragments (q pre-scaled by 0.125*log2e in QKV epilogue)
    uint32_t qh[4][4], ql[4][4];
    const int r = l >> 2;
    const int row0 = qb + w * 16 + r;
    {
        const size_t a0 = (size_t)(rowb + row0) * 3072 + qcol;
        const size_t a1 = a0 + (size_t)8 * 3072;
        #pragma unroll
        for (int ks = 0; ks < 4; ks++) {
            const int c0 = ks * 16 + (l & 3) * 2;
            qh[ks][0] = *reinterpret_cast<const uint32_t*>(QKVhi + a0 + c0);
            qh[ks][1] = *reinterpret_cast<const uint32_t*>(QKVhi + a1 + c0);
            qh[ks][2] = *reinterpret_cast<const uint32_t*>(QKVhi + a0 + c0 + 8);
            qh[ks][3] = *reinterpret_cast<const uint32_t*>(QKVhi + a1 + c0 + 8);
            ql[ks][0] = *reinterpret_cast<const uint32_t*>(QKVlo + a0 + c0);
            ql[ks][1] = *reinterpret_cast<const uint32_t*>(QKVlo + a1 + c0);
            ql[ks][2] = *reinterpret_cast<const uint32_t*>(QKVlo + a0 + c0 + 8);
            ql[ks][3] = *reinterpret_cast<const uint32_t*>(QKVlo + a1 + c0 + 8);
        }
    }

    float O[8][4];
    #pragma unroll
    for (int t = 0; t < 8; t++)
        #pragma unroll
        for (int i = 0; i < 4; i++) O[t][i] = 0.0f;
    float m0 = -CUDART_INF_F, m1 = -CUDART_INF_F, l0 = 0.0f, l1 = 0.0f;

    const unsigned* mr0 = mbits + (size_t)(rowb + row0) * (Tv / 32);
    const unsigned* mr1 = mr0 + (size_t)8 * (Tv / 32);

    auto issue = [&](int kt, int st) {
        const uint32_t sb = s0a + st * AST;
        #pragma unroll
        for (int i = 0; i < 4; i++) {
            const int vv = tid + 128 * i;            // 0..511
            const int rr = vv >> 3, c16 = vv & 7;
            const uint32_t sw = SMEM_SWIZZLE_128B((uint32_t)(rr * 128 + c16 * 16));
            const size_t gk = (size_t)(rowb + kt + rr) * 3072 + kcol + c16 * 8;
            const size_t gv = (size_t)(rowb + kt + rr) * 3072 + vcol + c16 * 8;
            CP_ASYNC16(sb + sw,          (const void*)(QKVhi + gk));
            CP_ASYNC16(sb + 8192 + sw,   (const void*)(QKVlo + gk));
            CP_ASYNC16(sb + 16384 + sw,  (const void*)(QKVhi + gv));
            CP_ASYNC16(sb + 24576 + sw,  (const void*)(QKVlo + gv));
        }
    };

    issue(0, 0); CP_COMMIT();

    #pragma unroll 1
    for (int kt = 0; kt < Tv; kt += 64) {
        const int st = (kt >> 6) & 1;
        CP_WAIT(0);
        __syncthreads();
        if (kt + 64 < Tv) { issue(kt + 64, st ^ 1); CP_COMMIT(); }

        const uint32_t kb = s0a + st * AST;
        const uint32_t vb = kb + 16384;

        // ---- S = Q K^T (3-pass split) ----
        float S[8][4];
        #pragma unroll
        for (int t = 0; t < 8; t++)
            #pragma unroll
            for (int i = 0; i < 4; i++) S[t][i] = 0.0f;

        #pragma unroll
        for (int ks = 0; ks < 4; ks++) {
            uint32_t bh[8][2], bl[8][2];
            #pragma unroll
            for (int j = 0; j < 4; j++) {
                const int nr = j * 16 + (l & 7) + ((l >> 4) & 1) * 8;
                const uint32_t off = SMEM_SWIZZLE_128B(
                    (uint32_t)(nr * 128 + ks * 32 + ((l >> 3) & 1) * 16));
                uint32_t r0, r1, r2, r3;
                ldsm4(kb + off, r0, r1, r2, r3);
                bh[2*j][0] = r0; bh[2*j][1] = r1; bh[2*j+1][0] = r2; bh[2*j+1][1] = r3;
                ldsm4(kb + 8192 + off, r0, r1, r2, r3);
                bl[2*j][0] = r0; bl[2*j][1] = r1; bl[2*j+1][0] = r2; bl[2*j+1][1] = r3;
            }
            #pragma unroll
            for (int t = 0; t < 8; t++) {
                mma16816(S[t], qh[ks], bh[t]);
                mma16816(S[t], qh[ks], bl[t]);
                mma16816(S[t], ql[ks], bh[t]);
            }
        }

        // ---- mask ----
        const int kw = kt >> 5;
        const unsigned w00 = mr0[kw], w01 = mr0[kw + 1];
        const unsigned w10 = mr1[kw], w11 = mr1[kw + 1];
        #pragma unroll
        for (int t = 0; t < 8; t++) {
            const int c = (t & 3) * 8 + (l & 3) * 2;
            const unsigned wa = (t < 4) ? w00 : w01;
            const unsigned wb = (t < 4) ? w10 : w11;
            if (!((wa >> c) & 1u))       S[t][0] -= MASK_PEN;
            if (!((wa >> (c + 1)) & 1u)) S[t][1] -= MASK_PEN;
            if (!((wb >> c) & 1u))       S[t][2] -= MASK_PEN;
            if (!((wb >> (c + 1)) & 1u)) S[t][3] -= MASK_PEN;
        }

        // ---- online softmax (log2 domain) ----
        float mx0 = -CUDART_INF_F, mx1 = -CUDART_INF_F;
        #pragma unroll
        for (int t = 0; t < 8; t++) {
            mx0 = fmaxf(mx0, fmaxf(S[t][0], S[t][1]));
            mx1 = fmaxf(mx1, fmaxf(S[t][2], S[t][3]));
        }
        mx0 = fmaxf(mx0, __shfl_xor_sync(0xffffffffu, mx0, 1));
        mx0 = fmaxf(mx0, __shfl_xor_sync(0xffffffffu, mx0, 2));
        mx1 = fmaxf(mx1, __shfl_xor_sync(0xffffffffu, mx1, 1));
        mx1 = fmaxf(mx1, __shfl_xor_sync(0xffffffffu, mx1, 2));

        const float mn0 = fmaxf(m0, mx0), mn1 = fmaxf(m1, mx1);
        const float sc0 = ex2f(m0 - mn0), sc1 = ex2f(m1 - mn1);
        m0 = mn0; m1 = mn1;
        l0 *= sc0; l1 *= sc1;

        #pragma unroll
        for (int t = 0; t < 8; t++) {
            S[t][0] = ex2f(S[t][0] - m0);
            S[t][1] = ex2f(S[t][1] - m0);
            S[t][2] = ex2f(S[t][2] - m1);
            S[t][3] = ex2f(S[t][3] - m1);
            l0 += S[t][0] + S[t][1];
            l1 += S[t][2] + S[t][3];
            O[t][0] *= sc0; O[t][1] *= sc0; O[t][2] *= sc1; O[t][3] *= sc1;
        }

        // ---- O += P V (3-pass split; V via ldmatrix.trans) ----
        #pragma unroll
        for (int ks = 0; ks < 4; ks++) {
            uint32_t ph[4], pl[4];
            split2(S[2*ks][0],   S[2*ks][1],   ph[0], pl[0]);
            split2(S[2*ks][2],   S[2*ks][3],   ph[1], pl[1]);
            split2(S[2*ks+1][0], S[2*ks+1][1], ph[2], pl[2]);
            split2(S[2*ks+1][2], S[2*ks+1][3], ph[3], pl[3]);

            uint32_t vh[8][2], vl[8][2];
            const int vr = ks * 16 + (l & 7) + ((l >> 3) & 1) * 8;
            #pragma unroll
            for (int j = 0; j < 4; j++) {
                const uint32_t off = SMEM_SWIZZLE_128B(
                    (uint32_t)(vr * 128 + (j * 16 + ((l >> 4) & 1) * 8) * 2));
                uint32_t r0, r1, r2, r3;
                ldsm4t(vb + off, r0, r1, r2, r3);
                vh[2*j][0] = r0; vh[2*j][1] = r1; vh[2*j+1][0] = r2; vh[2*j+1][1] = r3;
                ldsm4t(vb + 8192 + off, r0, r1, r2, r3);
                vl[2*j][0] = r0; vl[2*j][1] = r1; vl[2*j+1][0] = r2; vl[2*j+1][1] = r3;
            }
            #pragma unroll
            for (int t = 0; t < 8; t++) {
                mma16816(O[t], ph, vh[t]);
                mma16816(O[t], ph, vl[t]);
                mma16816(O[t], pl, vh[t]);
            }
        }
    }

    // ---- finalize: normalize and emit y hi/lo ----
    l0 += __shfl_xor_sync(0xffffffffu, l0, 1);
    l0 += __shfl_xor_sync(0xffffffffu, l0, 2);
    l1 += __shfl_xor_sync(0xffffffffu, l1, 1);
    l1 += __shfl_xor_sync(0xffffffffu, l1, 2);
    const float inv0 = 1.0f / l0, inv1 = 1.0f / l1;

    const size_t y0 = (size_t)(rowb + row0) * Dv + h * 64;
    const size_t y1 = y0 + (size_t)8 * Dv;
    #pragma unroll
    for (int t = 0; t < 8; t++) {
        const int col = t * 8 + (l & 3) * 2;
        uint32_t hw, lw;
        split2(O[t][0] * inv0, O[t][1] * inv0, hw, lw);
        *reinterpret_cast<uint32_t*>(Yhi + y0 + col) = hw;
        *reinterpret_cast<uint32_t*>(Ylo + y0 + col) = lw;
        split2(O[t][2] * inv1, O[t][3] * inv1, hw, lw);
        *reinterpret_cast<uint32_t*>(Yhi + y1 + col) = hw;
        *reinterpret_cast<uint32_t*>(Ylo + y1 + col) = lw;
    }
}

// ---------------------------------------------------------------------------
extern "C" void kernel_launch(void* const* d_in, const int* in_sizes, int n_in,
                              void* d_out, int out_size)
{
    const float* x        = (const float*)d_in[0];
    const int*   src_mask = (const int*)  d_in[1];
    const float* ln_gamma = (const float*)d_in[2];
    const float* ln_beta  = (const float*)d_in[3];
    const float* Wq = (const float*)d_in[4];
    const float* bq = (const float*)d_in[5];
    const float* Wk = (const float*)d_in[6];
    const float* bk = (const float*)d_in[7];
    const float* Wv = (const float*)d_in[8];
    const float* bv = (const float*)d_in[9];
    const float* Wo = (const float*)d_in[10];
    const float* bo = (const float*)d_in[11];
    float* out = (float*)d_out;

    __nv_bfloat16 *xnhi, *xnlo, *yhi, *ylo, *qkvhi, *qkvlo;
    unsigned* mbits;
    cudaGetSymbolAddress((void**)&xnhi,  g_xnhi);
    cudaGetSymbolAddress((void**)&xnlo,  g_xnlo);
    cudaGetSymbolAddress((void**)&yhi,   g_yhi);
    cudaGetSymbolAddress((void**)&ylo,   g_ylo);
    cudaGetSymbolAddress((void**)&qkvhi, g_qkvhi);
    cudaGetSymbolAddress((void**)&qkvlo, g_qkvlo);
    cudaGetSymbolAddress((void**)&mbits, g_mbits);

    cudaFuncSetAttribute(gemm_tc_kernel<true>,  cudaFuncAttributeMaxDynamicSharedMemorySize, SMEM_DYN);
    cudaFuncSetAttribute(gemm_tc_kernel<false>, cudaFuncAttributeMaxDynamicSharedMemorySize, SMEM_DYN);
    cudaFuncSetAttribute(attn_tc_kernel,        cudaFuncAttributeMaxDynamicSharedMemorySize, ASMEM);

    // 1. pack mask bits
    pack_mask_kernel<<<NWORDS / 8, 256>>>(src_mask, mbits);

    // 2. LayerNorm -> bf16 hi/lo
    ln_kernel<<<MROWS, 128>>>(x, ln_gamma, ln_beta, xnhi, xnlo);

    // 3. weight transpose + hi/lo conversion (Wq, Wk, Wv, Wo)
    wconv_kernel<<<dim3(Dv / 32, Dv / 32, 4), 256>>>(Wq, Wk, Wv, Wo);

    // 4. fused QKV projection -> bf16 hi/lo (q pre-scaled by 0.125*log2e)
    gemm_tc_kernel<true><<<dim3(24, 32), 256, SMEM_DYN>>>(
        xnhi, xnlo, 0, nullptr, nullptr, qkvhi, qkvlo, bq, bk, bv);

    // 5. tensor-core masked flash attention (emits y hi/lo)
    attn_tc_kernel<<<dim3(Tv / 64, Hv, Bv), 128, ASMEM>>>(qkvhi, qkvlo, mbits, yhi, ylo);

    // 6. output projection + bias + residual (fp32 out)
    gemm_tc_kernel<false><<<dim3(8, 32), 256, SMEM_DYN>>>(
        yhi, ylo, 3072, out, x, nullptr, nullptr, bo, bo, bo);
}

// round 11
// speedup vs baseline: 5.1213x; 1.3014x over previous
#include <cuda_runtime.h>
#include <cuda_fp16.h>
#include <math_constants.h>
#include <cstdint>

#define Bv 2
#define Tv 2048
#define Dv 1024
#define Hv 16
#define DHv 64
constexpr int MROWS = Bv * Tv;               // 4096
constexpr int NWORDS = Bv * Tv * (Tv / 32);  // 262144

// ---------------- scratch (__device__ globals; no allocation allowed) -------
__device__ __half g_xnhi[MROWS * Dv];
__device__ __half g_wthi[4 * Dv * Dv];   // [Wq^T; Wk^T; Wv^T; Wo^T] rows=[n], cols=[k]
__device__ __half g_wtlo[4 * Dv * Dv];
__device__ __half g_qkvhi[(size_t)MROWS * 3072];  // [row][q|k|v]
__device__ __half g_qkvlo[(size_t)MROWS * 3072];
__device__ __half g_yhi[MROWS * Dv];
__device__ unsigned g_mbits[NWORDS];

// ---------------- helpers ----------------------------------------------------
__device__ __forceinline__ uint32_t smem_to_u32(const void* p) {
    uint32_t a;
    asm("{ .reg .u64 t; cvta.to.shared.u64 t, %1; cvt.u32.u64 %0, t; }" : "=r"(a) : "l"(p));
    return a;
}

#define SMEM_SWIZZLE_128B(o) ((o) ^ (((o) >> 3) & 0x70))
#define SMEM_SWIZZLE_64B(o)  ((o) ^ (((o) >> 3) & 0x30))

#define CP_ASYNC16(smem_u32, gptr) \
    asm volatile("cp.async.cg.shared.global [%0], [%1], 16;" \
                 :: "r"(smem_u32), "l"(gptr) : "memory")
#define CP_COMMIT() asm volatile("cp.async.commit_group;" ::: "memory")
#define CP_WAIT(n)  asm volatile("cp.async.wait_group %0;" :: "n"(n) : "memory")

__device__ __forceinline__ void ldsm4(uint32_t addr, uint32_t& r0, uint32_t& r1,
                                      uint32_t& r2, uint32_t& r3) {
    asm volatile("ldmatrix.sync.aligned.m8n8.x4.shared.b16 {%0,%1,%2,%3}, [%4];"
                 : "=r"(r0), "=r"(r1), "=r"(r2), "=r"(r3) : "r"(addr));
}
__device__ __forceinline__ void ldsm4t(uint32_t addr, uint32_t& r0, uint32_t& r1,
                                       uint32_t& r2, uint32_t& r3) {
    asm volatile("ldmatrix.sync.aligned.m8n8.x4.trans.shared.b16 {%0,%1,%2,%3}, [%4];"
                 : "=r"(r0), "=r"(r1), "=r"(r2), "=r"(r3) : "r"(addr));
}

__device__ __forceinline__ void mma16816(float* c, const uint32_t* a, const uint32_t* b) {
    asm volatile(
        "mma.sync.aligned.m16n8k16.row.col.f32.f16.f16.f32 "
        "{%0,%1,%2,%3}, {%4,%5,%6,%7}, {%8,%9}, {%0,%1,%2,%3};"
        : "+f"(c[0]), "+f"(c[1]), "+f"(c[2]), "+f"(c[3])
        : "r"(a[0]), "r"(a[1]), "r"(a[2]), "r"(a[3]), "r"(b[0]), "r"(b[1]));
}

__device__ __forceinline__ float ex2f(float x) {
    float r;
    asm("ex2.approx.ftz.f32 %0, %1;" : "=f"(r) : "f"(x));
    return r;
}

// split a float pair into packed fp16 hi + fp16 lo (residual) words
__device__ __forceinline__ void split2(float a, float b, uint32_t& hi, uint32_t& lo) {
    __half2 h = __floats2half2_rn(a, b);
    float la = a - __half2float(__low2half(h));
    float lb = b - __half2float(__high2half(h));
    __half2 l2 = __floats2half2_rn(la, lb);
    hi = *reinterpret_cast<uint32_t*>(&h);
    lo = *reinterpret_cast<uint32_t*>(&l2);
}

__device__ __forceinline__ uint32_t pack2h(float a, float b) {
    __half2 h = __floats2half2_rn(a, b);
    return *reinterpret_cast<uint32_t*>(&h);
}

// ---------------------------------------------------------------------------
// Pack src_mask into bitmask words (bit set = attend)
// ---------------------------------------------------------------------------
__global__ void __launch_bounds__(256) pack_mask_kernel(const int* __restrict__ mask,
                                                        unsigned* __restrict__ bits)
{
    int w = blockIdx.x * (blockDim.x >> 5) + (threadIdx.x >> 5);
    int lane = threadIdx.x & 31;
    int v = mask[(size_t)w * 32 + lane];
    unsigned b = __ballot_sync(0xffffffffu, v != 0);
    if (lane == 0) bits[w] = b;
}

// ---------------------------------------------------------------------------
// LayerNorm -> fp16 output (hi only; GEMM corrects only the W operand)
// ---------------------------------------------------------------------------
__global__ void __launch_bounds__(128) ln_kernel(const float* __restrict__ x,
                                                 const float* __restrict__ gamma,
                                                 const float* __restrict__ beta,
                                                 __half* __restrict__ ohi)
{
    const int row = blockIdx.x;
    const int t = threadIdx.x;
    const float4* xr = reinterpret_cast<const float4*>(x + (size_t)row * Dv);
    float4 v0 = xr[t], v1 = xr[t + 128];

    float s  = v0.x + v0.y + v0.z + v0.w + v1.x + v1.y + v1.z + v1.w;
    float ss = v0.x*v0.x + v0.y*v0.y + v0.z*v0.z + v0.w*v0.w
             + v1.x*v1.x + v1.y*v1.y + v1.z*v1.z + v1.w*v1.w;

    #pragma unroll
    for (int off = 16; off > 0; off >>= 1) {
        s  += __shfl_xor_sync(0xffffffffu, s,  off);
        ss += __shfl_xor_sync(0xffffffffu, ss, off);
    }
    __shared__ float red[8];
    int warp = t >> 5, lane = t & 31;
    if (lane == 0) { red[warp] = s; red[warp + 4] = ss; }
    __syncthreads();
    s  = red[0] + red[1] + red[2] + red[3];
    ss = red[4] + red[5] + red[6] + red[7];

    const float mean = s * (1.0f / Dv);
    const float var  = ss * (1.0f / Dv) - mean * mean;
    const float rstd = rsqrtf(var + 1e-5f);

    const float4* g4 = reinterpret_cast<const float4*>(gamma);
    const float4* b4 = reinterpret_cast<const float4*>(beta);
    float4 g0 = g4[t], g1 = g4[t + 128];
    float4 e0 = b4[t], e1 = b4[t + 128];
    uint2 hv;
    hv.x = pack2h((v0.x - mean) * rstd * g0.x + e0.x, (v0.y - mean) * rstd * g0.y + e0.y);
    hv.y = pack2h((v0.z - mean) * rstd * g0.z + e0.z, (v0.w - mean) * rstd * g0.w + e0.w);
    *reinterpret_cast<uint2*>(ohi + (size_t)row * Dv + t * 4) = hv;
    hv.x = pack2h((v1.x - mean) * rstd * g1.x + e1.x, (v1.y - mean) * rstd * g1.y + e1.y);
    hv.y = pack2h((v1.z - mean) * rstd * g1.z + e1.z, (v1.w - mean) * rstd * g1.w + e1.w);
    *reinterpret_cast<uint2*>(ohi + (size_t)row * Dv + (t + 128) * 4) = hv;
}

// ---------------------------------------------------------------------------
// Weight transpose + fp16 hi/lo conversion: g_wt[z*1024 + n][k] = W_z[k][n]
// ---------------------------------------------------------------------------
__global__ void __launch_bounds__(256) wconv_kernel(const float* __restrict__ w0,
                                                    const float* __restrict__ w1,
                                                    const float* __restrict__ w2,
                                                    const float* __restrict__ w3)
{
    __shared__ float tile[32][33];
    const float* src = (blockIdx.z == 0) ? w0 : (blockIdx.z == 1) ? w1
                     : (blockIdx.z == 2) ? w2 : w3;
    int kt = blockIdx.x * 32, nt = blockIdx.y * 32;
    int tx = threadIdx.x & 31, ty = threadIdx.x >> 5;
    #pragma unroll
    for (int i = 0; i < 4; i++)
        tile[ty + 8 * i][tx] = src[(size_t)(kt + ty + 8 * i) * Dv + nt + tx];
    __syncthreads();
    size_t off = (size_t)blockIdx.z * Dv;
    #pragma unroll
    for (int i = 0; i < 4; i++) {
        int n = nt + ty + 8 * i, kk = kt + tx;
        float v = tile[tx][ty + 8 * i];
        __half hi = __float2half_rn(v);
        float lof = v - __half2float(hi);
        g_wthi[(off + n) * Dv + kk] = hi;
        g_wtlo[(off + n) * Dv + kk] = __float2half_rn(lof);
    }
}

// ---------------------------------------------------------------------------
// mma.sync fp16 2-pass GEMM. CTA tile 128x128, 8 warps (2x4), K-chunk 32,
// 4-stage cp.async pipeline, one barrier per chunk, 2 CTAs/SM.
//   C = Ah@Bh^T + Ah@Bl^T      (fp32 accum; W corrected, activations hi-only)
// ---------------------------------------------------------------------------
constexpr int GTILE = 8192;                  // one 128x32 fp16 tile
constexpr int STAGE = 3 * GTILE;             // Ah|Wh|Wl (24KB)
constexpr int NSTG = 4;
constexpr int SMEM_DYN = NSTG * STAGE + 1024;

template <bool HILO>
__global__ void __launch_bounds__(256, 2) gemm_tc_kernel(
    const __half* __restrict__ Ahi,
    int wrow_off,
    float* Cf, const float* res,
    __half* Chi, __half* Clo,
    const float* b0, const float* b1, const float* b2)
{
    extern __shared__ char dyns[];
    const uint32_t sraw = smem_to_u32(dyns);
    const uint32_t s0 = (sraw + 1023) & ~1023u;

    const int tid = threadIdx.x;
    const int bm = blockIdx.y * 128;
    const int bx = blockIdx.x;
    const int wrow = wrow_off + bx * 128;

    float acc[4][4][4];
    #pragma unroll
    for (int i = 0; i < 4; i++)
        #pragma unroll
        for (int j = 0; j < 4; j++)
            #pragma unroll
            for (int r = 0; r < 4; r++) acc[i][j][r] = 0.0f;

    // loaders: 3 tiles x 512 16B-vectors; each thread does 2 per tile
    const int lr  = tid >> 2;            // row 0..63 (then +64)
    const int lc8 = (tid & 3) * 8;       // fp16 col
    const uint32_t lcb = (tid & 3) * 16; // byte col

    auto issue_loads = [&](int c, int st) {
        const uint32_t sb = s0 + st * STAGE;
        #pragma unroll
        for (int i = 0; i < 2; i++) {
            const int r = lr + 64 * i;
            const uint32_t sw = SMEM_SWIZZLE_64B((uint32_t)(r * 64) + lcb);
            const size_t ga = (size_t)(bm + r) * Dv + c * 32 + lc8;
            const size_t gw = (size_t)(wrow + r) * Dv + c * 32 + lc8;
            CP_ASYNC16(sb + sw,             (const void*)(Ahi + ga));
            CP_ASYNC16(sb + GTILE + sw,     (const void*)(g_wthi + gw));
            CP_ASYNC16(sb + 2 * GTILE + sw, (const void*)(g_wtlo + gw));
        }
    };

    const int l = tid & 31;
    const int w = tid >> 5;
    const int wm = (w >> 2) * 64;
    const int wn = (w & 3) * 32;

    auto compute = [&](int st) {
        const uint32_t sb = s0 + st * STAGE;
        #pragma unroll
        for (int ks = 0; ks < 2; ks++) {
            uint32_t bh[4][2], bl[4][2];
            const int bkb = ks * 32 + ((l >> 3) & 1) * 16;
            #pragma unroll
            for (int j = 0; j < 2; j++) {
                const int nr = wn + j * 16 + (l & 7) + ((l >> 4) & 1) * 8;
                const uint32_t off = SMEM_SWIZZLE_64B((uint32_t)(nr * 64 + bkb));
                uint32_t r0, r1, r2, r3;
                ldsm4(sb + GTILE + off, r0, r1, r2, r3);
                bh[2 * j][0] = r0; bh[2 * j][1] = r1;
                bh[2 * j + 1][0] = r2; bh[2 * j + 1][1] = r3;
                ldsm4(sb + 2 * GTILE + off, r0, r1, r2, r3);
                bl[2 * j][0] = r0; bl[2 * j][1] = r1;
                bl[2 * j + 1][0] = r2; bl[2 * j + 1][1] = r3;
            }
            const int akb = ks * 32 + ((l >> 4) & 1) * 16;
            #pragma unroll
            for (int mt = 0; mt < 4; mt++) {
                uint32_t ah[4];
                const int row = wm + mt * 16 + (l & 7) + ((l >> 3) & 1) * 8;
                const uint32_t off = SMEM_SWIZZLE_64B((uint32_t)(row * 64 + akb));
                ldsm4(sb + off, ah[0], ah[1], ah[2], ah[3]);
                #pragma unroll
                for (int nt = 0; nt < 4; nt++) {
                    mma16816(acc[mt][nt], ah, bh[nt]);
                    mma16816(acc[mt][nt], ah, bl[nt]);
                }
            }
        }
    };

    issue_loads(0, 0); CP_COMMIT();
    issue_loads(1, 1); CP_COMMIT();
    issue_loads(2, 2); CP_COMMIT();
    #pragma unroll 1
    for (int c = 0; c < 32; c++) {
        if (c <= 29)      { CP_WAIT(2); }
        else if (c == 30) { CP_WAIT(1); }
        else              { CP_WAIT(0); }
        __syncthreads();
        if (c + 3 < 32) { issue_loads(c + 3, (c + 3) % NSTG); CP_COMMIT(); }
        compute(c % NSTG);
    }

    // ---- epilogue ----
    const int seg = bx >> 3;
    const float* bias = (seg == 0) ? b0 : (seg == 1) ? b1 : b2;
    // q is pre-scaled by 1/sqrt(dh) * log2(e) so softmax can use raw ex2
    const float scale = (HILO && seg == 0) ? 0.125f * 1.4426950408889634f : 1.0f;

    #pragma unroll
    for (int mt = 0; mt < 4; mt++) {
        #pragma unroll
        for (int nt = 0; nt < 4; nt++) {
            const int row = bm + wm + mt * 16 + (l >> 2);
            const int cseg = (bx & 7) * 128 + wn + nt * 8 + (l & 3) * 2;  // col within segment
            float2 bb = *reinterpret_cast<const float2*>(bias + cseg);
            float v0 = (acc[mt][nt][0] + bb.x) * scale;
            float v1 = (acc[mt][nt][1] + bb.y) * scale;
            float v2 = (acc[mt][nt][2] + bb.x) * scale;
            float v3 = (acc[mt][nt][3] + bb.y) * scale;
            if (HILO) {
                const size_t o0 = (size_t)row * 3072 + seg * 1024 + cseg;
                const size_t o1 = o0 + (size_t)8 * 3072;
                uint32_t hw, lw;
                split2(v0, v1, hw, lw);
                *reinterpret_cast<uint32_t*>(Chi + o0) = hw;
                *reinterpret_cast<uint32_t*>(Clo + o0) = lw;
                split2(v2, v3, hw, lw);
                *reinterpret_cast<uint32_t*>(Chi + o1) = hw;
                *reinterpret_cast<uint32_t*>(Clo + o1) = lw;
            } else {
                const size_t g0o = (size_t)row * Dv + cseg;
                const size_t g1o = g0o + (size_t)8 * Dv;
                float2 r0 = *reinterpret_cast<const float2*>(res + g0o);
                float2 r1 = *reinterpret_cast<const float2*>(res + g1o);
                *reinterpret_cast<float2*>(Cf + g0o) = make_float2(v0 + r0.x, v1 + r0.y);
                *reinterpret_cast<float2*>(Cf + g1o) = make_float2(v2 + r1.x, v3 + r1.y);
            }
        }
    }
}

// ---------------------------------------------------------------------------
// Tensor-core flash attention, fp16 2-pass:
//   S = qh.Kh + ql.Kh   (q corrected from registers; K hi-only in smem)
//   O += Ph.Vh + Pl.Vh  (P corrected in registers; V hi-only in smem)
// grid (T/64, H, B), 128 threads (4 warps x 16 queries).
// Double-buffered Khi|Vhi tiles (16KB/stage); one barrier per key-tile.
// ---------------------------------------------------------------------------
constexpr int AST = 16384;                   // Khi|Vhi tiles (8KB each)
constexpr int ASMEM = 2 * AST + 1024;
#define MASK_PEN 144269.50f                  // 100000 * log2(e)

__global__ void __launch_bounds__(128) attn_tc_kernel(
    const __half* __restrict__ QKVhi, const __half* __restrict__ QKVlo,
    const unsigned* __restrict__ mbits,
    __half* __restrict__ Yhi)
{
    extern __shared__ char dyns[];
    const uint32_t sraw = smem_to_u32(dyns);
    const uint32_t s0a = (sraw + 1023) & ~1023u;

    const int tid = threadIdx.x, l = tid & 31, w = tid >> 5;
    const int b = blockIdx.z, h = blockIdx.y;
    const int qb = blockIdx.x * 64;
    const int rowb = b * Tv;
    const int qcol = h * 64, kcol = 1024 + h * 64, vcol = 2048 + h * 64;

    // Q fragments (q pre-scaled by 0.125*log2e in QKV epilogue)
    uint32_t qh[4][4], ql[4][4];
    const int r = l >> 2;
    const int row0 = qb + w * 16 + r;
    {
        const size_t a0 = (size_t)(rowb + row0) * 3072 + qcol;
        const size_t a1 = a0 + (size_t)8 * 3072;
        #pragma unroll
        for (int ks = 0; ks < 4; ks++) {
            const int c0 = ks * 16 + (l & 3) * 2;
            qh[ks][0] = *reinterpret_cast<const uint32_t*>(QKVhi + a0 + c0);
            qh[ks][1] = *reinterpret_cast<const uint32_t*>(QKVhi + a1 + c0);
            qh[ks][2] = *reinterpret_cast<const uint32_t*>(QKVhi + a0 + c0 + 8);
            qh[ks][3] = *reinterpret_cast<const uint32_t*>(QKVhi + a1 + c0 + 8);
            ql[ks][0] = *reinterpret_cast<const uint32_t*>(QKVlo + a0 + c0);
            ql[ks][1] = *reinterpret_cast<const uint32_t*>(QKVlo + a1 + c0);
            ql[ks][2] = *reinterpret_cast<const uint32_t*>(QKVlo + a0 + c0 + 8);
            ql[ks][3] = *reinterpret_cast<const uint32_t*>(QKVlo + a1 + c0 + 8);
        }
    }

    float O[8][4];
    #pragma unroll
    for (int t = 0; t < 8; t++)
        #pragma unroll
        for (int i = 0; i < 4; i++) O[t][i] = 0.0f;
    float m0 = -CUDART_INF_F, m1 = -CUDART_INF_F, l0 = 0.0f, l1 = 0.0f;

    const unsigned* mr0 = mbits + (size_t)(rowb + row0) * (Tv / 32);
    const unsigned* mr1 = mr0 + (size_t)8 * (Tv / 32);

    auto issue = [&](int kt, int st) {
        const uint32_t sb = s0a + st * AST;
        #pragma unroll
        for (int i = 0; i < 4; i++) {
            const int vv = tid + 128 * i;            // 0..511
            const int rr = vv >> 3, c16 = vv & 7;
            const uint32_t sw = SMEM_SWIZZLE_128B((uint32_t)(rr * 128 + c16 * 16));
            const size_t gk = (size_t)(rowb + kt + rr) * 3072 + kcol + c16 * 8;
            const size_t gv = (size_t)(rowb + kt + rr) * 3072 + vcol + c16 * 8;
            CP_ASYNC16(sb + sw,         (const void*)(QKVhi + gk));
            CP_ASYNC16(sb + 8192 + sw,  (const void*)(QKVhi + gv));
        }
    };

    issue(0, 0); CP_COMMIT();

    #pragma unroll 1
    for (int kt = 0; kt < Tv; kt += 64) {
        const int st = (kt >> 6) & 1;
        CP_WAIT(0);
        __syncthreads();
        if (kt + 64 < Tv) { issue(kt + 64, st ^ 1); CP_COMMIT(); }

        const uint32_t kb = s0a + st * AST;
        const uint32_t vb = kb + 8192;

        // ---- S = Q K^T (2-pass: q corrected) ----
        float S[8][4];
        #pragma unroll
        for (int t = 0; t < 8; t++)
            #pragma unroll
            for (int i = 0; i < 4; i++) S[t][i] = 0.0f;

        #pragma unroll
        for (int ks = 0; ks < 4; ks++) {
            uint32_t bh[8][2];
            #pragma unroll
            for (int j = 0; j < 4; j++) {
                const int nr = j * 16 + (l & 7) + ((l >> 4) & 1) * 8;
                const uint32_t off = SMEM_SWIZZLE_128B(
                    (uint32_t)(nr * 128 + ks * 32 + ((l >> 3) & 1) * 16));
                uint32_t r0, r1, r2, r3;
                ldsm4(kb + off, r0, r1, r2, r3);
                bh[2*j][0] = r0; bh[2*j][1] = r1; bh[2*j+1][0] = r2; bh[2*j+1][1] = r3;
            }
            #pragma unroll
            for (int t = 0; t < 8; t++) {
                mma16816(S[t], qh[ks], bh[t]);
                mma16816(S[t], ql[ks], bh[t]);
            }
        }

        // ---- mask ----
        const int kw = kt >> 5;
        const unsigned w00 = mr0[kw], w01 = mr0[kw + 1];
        const unsigned w10 = mr1[kw], w11 = mr1[kw + 1];
        #pragma unroll
        for (int t = 0; t < 8; t++) {
            const int c = (t & 3) * 8 + (l & 3) * 2;
            const unsigned wa = (t < 4) ? w00 : w01;
            const unsigned wb = (t < 4) ? w10 : w11;
            if (!((wa >> c) & 1u))       S[t][0] -= MASK_PEN;
            if (!((wa >> (c + 1)) & 1u)) S[t][1] -= MASK_PEN;
            if (!((wb >> c) & 1u))       S[t][2] -= MASK_PEN;
            if (!((wb >> (c + 1)) & 1u)) S[t][3] -= MASK_PEN;
        }

        // ---- online softmax (log2 domain) ----
        float mx0 = -CUDART_INF_F, mx1 = -CUDART_INF_F;
        #pragma unroll
        for (int t = 0; t < 8; t++) {
            mx0 = fmaxf(mx0, fmaxf(S[t][0], S[t][1]));
            mx1 = fmaxf(mx1, fmaxf(S[t][2], S[t][3]));
        }
        mx0 = fmaxf(mx0, __shfl_xor_sync(0xffffffffu, mx0, 1));
        mx0 = fmaxf(mx0, __shfl_xor_sync(0xffffffffu, mx0, 2));
        mx1 = fmaxf(mx1, __shfl_xor_sync(0xffffffffu, mx1, 1));
        mx1 = fmaxf(mx1, __shfl_xor_sync(0xffffffffu, mx1, 2));

        const float mn0 = fmaxf(m0, mx0), mn1 = fmaxf(m1, mx1);
        const float sc0 = ex2f(m0 - mn0), sc1 = ex2f(m1 - mn1);
        m0 = mn0; m1 = mn1;
        l0 *= sc0; l1 *= sc1;

        #pragma unroll
        for (int t = 0; t < 8; t++) {
            S[t][0] = ex2f(S[t][0] - m0);
            S[t][1] = ex2f(S[t][1] - m0);
            S[t][2] = ex2f(S[t][2] - m1);
            S[t][3] = ex2f(S[t][3] - m1);
            l0 += S[t][0] + S[t][1];
            l1 += S[t][2] + S[t][3];
            O[t][0] *= sc0; O[t][1] *= sc0; O[t][2] *= sc1; O[t][3] *= sc1;
        }

        // ---- O += P V (2-pass: P corrected; V via ldmatrix.trans) ----
        #pragma unroll
        for (int ks = 0; ks < 4; ks++) {
            uint32_t ph[4], pl[4];
            split2(S[2*ks][0],   S[2*ks][1],   ph[0], pl[0]);
            split2(S[2*ks][2],   S[2*ks][3],   ph[1], pl[1]);
            split2(S[2*ks+1][0], S[2*ks+1][1], ph[2], pl[2]);
            split2(S[2*ks+1][2], S[2*ks+1][3], ph[3], pl[3]);

            uint32_t vh[8][2];
            const int vr = ks * 16 + (l & 7) + ((l >> 3) & 1) * 8;
            #pragma unroll
            for (int j = 0; j < 4; j++) {
                const uint32_t off = SMEM_SWIZZLE_128B(
                    (uint32_t)(vr * 128 + (j * 16 + ((l >> 4) & 1) * 8) * 2));
                uint32_t r0, r1, r2, r3;
                ldsm4t(vb + off, r0, r1, r2, r3);
                vh[2*j][0] = r0; vh[2*j][1] = r1; vh[2*j+1][0] = r2; vh[2*j+1][1] = r3;
            }
            #pragma unroll
            for (int t = 0; t < 8; t++) {
                mma16816(O[t], ph, vh[t]);
                mma16816(O[t], pl, vh[t]);
            }
        }
    }

    // ---- finalize: normalize and emit y (hi only) ----
    l0 += __shfl_xor_sync(0xffffffffu, l0, 1);
    l0 += __shfl_xor_sync(0xffffffffu, l0, 2);
    l1 += __shfl_xor_sync(0xffffffffu, l1, 1);
    l1 += __shfl_xor_sync(0xffffffffu, l1, 2);
    const float inv0 = 1.0f / l0, inv1 = 1.0f / l1;

    const size_t y0 = (size_t)(rowb + row0) * Dv + h * 64;
    const size_t y1 = y0 + (size_t)8 * Dv;
    #pragma unroll
    for (int t = 0; t < 8; t++) {
        const int col = t * 8 + (l & 3) * 2;
        *reinterpret_cast<uint32_t*>(Yhi + y0 + col) =
            pack2h(O[t][0] * inv0, O[t][1] * inv0);
        *reinterpret_cast<uint32_t*>(Yhi + y1 + col) =
            pack2h(O[t][2] * inv1, O[t][3] * inv1);
    }
}

// ---------------------------------------------------------------------------
extern "C" void kernel_launch(void* const* d_in, const int* in_sizes, int n_in,
                              void* d_out, int out_size)
{
    const float* x        = (const float*)d_in[0];
    const int*   src_mask = (const int*)  d_in[1];
    const float* ln_gamma = (const float*)d_in[2];
    const float* ln_beta  = (const float*)d_in[3];
    const float* Wq = (const float*)d_in[4];
    const float* bq = (const float*)d_in[5];
    const float* Wk = (const float*)d_in[6];
    const float* bk = (const float*)d_in[7];
    const float* Wv = (const float*)d_in[8];
    const float* bv = (const float*)d_in[9];
    const float* Wo = (const float*)d_in[10];
    const float* bo = (const float*)d_in[11];
    float* out = (float*)d_out;

    __half *xnhi, *yhi, *qkvhi, *qkvlo;
    unsigned* mbits;
    cudaGetSymbolAddress((void**)&xnhi,  g_xnhi);
    cudaGetSymbolAddress((void**)&yhi,   g_yhi);
    cudaGetSymbolAddress((void**)&qkvhi, g_qkvhi);
    cudaGetSymbolAddress((void**)&qkvlo, g_qkvlo);
    cudaGetSymbolAddress((void**)&mbits, g_mbits);

    cudaFuncSetAttribute(gemm_tc_kernel<true>,  cudaFuncAttributeMaxDynamicSharedMemorySize, SMEM_DYN);
    cudaFuncSetAttribute(gemm_tc_kernel<false>, cudaFuncAttributeMaxDynamicSharedMemorySize, SMEM_DYN);
    cudaFuncSetAttribute(attn_tc_kernel,        cudaFuncAttributeMaxDynamicSharedMemorySize, ASMEM);

    // 1. pack mask bits
    pack_mask_kernel<<<NWORDS / 8, 256>>>(src_mask, mbits);

    // 2. LayerNorm -> fp16
    ln_kernel<<<MROWS, 128>>>(x, ln_gamma, ln_beta, xnhi);

    // 3. weight transpose + fp16 hi/lo conversion (Wq, Wk, Wv, Wo)
    wconv_kernel<<<dim3(Dv / 32, Dv / 32, 4), 256>>>(Wq, Wk, Wv, Wo);

    // 4. fused QKV projection -> fp16 hi/lo (q pre-scaled by 0.125*log2e)
    gemm_tc_kernel<true><<<dim3(24, 32), 256, SMEM_DYN>>>(
        xnhi, 0, nullptr, nullptr, qkvhi, qkvlo, bq, bk, bv);

    // 5. tensor-core masked flash attention (emits y fp16)
    attn_tc_kernel<<<dim3(Tv / 64, Hv, Bv), 128, ASMEM>>>(qkvhi, qkvlo, mbits, yhi);

    // 6. output projection + bias + residual (fp32 out)
    gemm_tc_kernel<false><<<dim3(8, 32), 256, SMEM_DYN>>>(
        yhi, 3072, out, x, nullptr, nullptr, bo, bo, bo);
}

// round 13
// speedup vs baseline: 8.2373x; 1.6084x over previous
#include <cuda_runtime.h>
#include <cuda_fp16.h>
#include <math_constants.h>
#include <cstdint>

#define Bv 2
#define Tv 2048
#define Dv 1024
#define Hv 16
#define DHv 64
constexpr int MROWS = Bv * Tv;               // 4096
constexpr int NWORDS = Bv * Tv * (Tv / 32);  // 262144

// ---------------- scratch (__device__ globals; no allocation allowed) -------
__device__ __half g_xnhi[MROWS * Dv];
__device__ __half g_wthi[4 * Dv * Dv];   // [Wq^T; Wk^T; Wv^T; Wo^T] rows=[n], cols=[k]
__device__ __half g_qkvhi[(size_t)MROWS * 3072];  // [row][q|k|v]
__device__ __half g_yhi[MROWS * Dv];
__device__ unsigned g_mbits[NWORDS];

// ---------------- helpers ----------------------------------------------------
__device__ __forceinline__ uint32_t smem_to_u32(const void* p) {
    uint32_t a;
    asm("{ .reg .u64 t; cvta.to.shared.u64 t, %1; cvt.u32.u64 %0, t; }" : "=r"(a) : "l"(p));
    return a;
}

#define SMEM_SWIZZLE_128B(o) ((o) ^ (((o) >> 3) & 0x70))
#define SMEM_SWIZZLE_64B(o)  ((o) ^ (((o) >> 3) & 0x30))

#define CP_ASYNC16(smem_u32, gptr) \
    asm volatile("cp.async.cg.shared.global [%0], [%1], 16;" \
                 :: "r"(smem_u32), "l"(gptr) : "memory")
#define CP_COMMIT() asm volatile("cp.async.commit_group;" ::: "memory")
#define CP_WAIT(n)  asm volatile("cp.async.wait_group %0;" :: "n"(n) : "memory")

__device__ __forceinline__ void ldsm4(uint32_t addr, uint32_t& r0, uint32_t& r1,
                                      uint32_t& r2, uint32_t& r3) {
    asm volatile("ldmatrix.sync.aligned.m8n8.x4.shared.b16 {%0,%1,%2,%3}, [%4];"
                 : "=r"(r0), "=r"(r1), "=r"(r2), "=r"(r3) : "r"(addr));
}
__device__ __forceinline__ void ldsm4t(uint32_t addr, uint32_t& r0, uint32_t& r1,
                                       uint32_t& r2, uint32_t& r3) {
    asm volatile("ldmatrix.sync.aligned.m8n8.x4.trans.shared.b16 {%0,%1,%2,%3}, [%4];"
                 : "=r"(r0), "=r"(r1), "=r"(r2), "=r"(r3) : "r"(addr));
}

__device__ __forceinline__ void mma16816(float* c, const uint32_t* a, const uint32_t* b) {
    asm volatile(
        "mma.sync.aligned.m16n8k16.row.col.f32.f16.f16.f32 "
        "{%0,%1,%2,%3}, {%4,%5,%6,%7}, {%8,%9}, {%0,%1,%2,%3};"
        : "+f"(c[0]), "+f"(c[1]), "+f"(c[2]), "+f"(c[3])
        : "r"(a[0]), "r"(a[1]), "r"(a[2]), "r"(a[3]), "r"(b[0]), "r"(b[1]));
}

__device__ __forceinline__ float ex2f(float x) {
    float r;
    asm("ex2.approx.ftz.f32 %0, %1;" : "=f"(r) : "f"(x));
    return r;
}

__device__ __forceinline__ uint32_t pack2h(float a, float b) {
    __half2 h = __floats2half2_rn(a, b);
    return *reinterpret_cast<uint32_t*>(&h);
}

// ---------------------------------------------------------------------------
// Pack src_mask into bitmask words (bit set = attend)
// ---------------------------------------------------------------------------
__global__ void __launch_bounds__(256) pack_mask_kernel(const int* __restrict__ mask,
                                                        unsigned* __restrict__ bits)
{
    int w = blockIdx.x * (blockDim.x >> 5) + (threadIdx.x >> 5);
    int lane = threadIdx.x & 31;
    int v = mask[(size_t)w * 32 + lane];
    unsigned b = __ballot_sync(0xffffffffu, v != 0);
    if (lane == 0) bits[w] = b;
}

// ---------------------------------------------------------------------------
// LayerNorm -> fp16 output
// ---------------------------------------------------------------------------
__global__ void __launch_bounds__(128) ln_kernel(const float* __restrict__ x,
                                                 const float* __restrict__ gamma,
                                                 const float* __restrict__ beta,
                                                 __half* __restrict__ ohi)
{
    const int row = blockIdx.x;
    const int t = threadIdx.x;
    const float4* xr = reinterpret_cast<const float4*>(x + (size_t)row * Dv);
    float4 v0 = xr[t], v1 = xr[t + 128];

    float s  = v0.x + v0.y + v0.z + v0.w + v1.x + v1.y + v1.z + v1.w;
    float ss = v0.x*v0.x + v0.y*v0.y + v0.z*v0.z + v0.w*v0.w
             + v1.x*v1.x + v1.y*v1.y + v1.z*v1.z + v1.w*v1.w;

    #pragma unroll
    for (int off = 16; off > 0; off >>= 1) {
        s  += __shfl_xor_sync(0xffffffffu, s,  off);
        ss += __shfl_xor_sync(0xffffffffu, ss, off);
    }
    __shared__ float red[8];
    int warp = t >> 5, lane = t & 31;
    if (lane == 0) { red[warp] = s; red[warp + 4] = ss; }
    __syncthreads();
    s  = red[0] + red[1] + red[2] + red[3];
    ss = red[4] + red[5] + red[6] + red[7];

    const float mean = s * (1.0f / Dv);
    const float var  = ss * (1.0f / Dv) - mean * mean;
    const float rstd = rsqrtf(var + 1e-5f);

    const float4* g4 = reinterpret_cast<const float4*>(gamma);
    const float4* b4 = reinterpret_cast<const float4*>(beta);
    float4 g0 = g4[t], g1 = g4[t + 128];
    float4 e0 = b4[t], e1 = b4[t + 128];
    uint2 hv;
    hv.x = pack2h((v0.x - mean) * rstd * g0.x + e0.x, (v0.y - mean) * rstd * g0.y + e0.y);
    hv.y = pack2h((v0.z - mean) * rstd * g0.z + e0.z, (v0.w - mean) * rstd * g0.w + e0.w);
    *reinterpret_cast<uint2*>(ohi + (size_t)row * Dv + t * 4) = hv;
    hv.x = pack2h((v1.x - mean) * rstd * g1.x + e1.x, (v1.y - mean) * rstd * g1.y + e1.y);
    hv.y = pack2h((v1.z - mean) * rstd * g1.z + e1.z, (v1.w - mean) * rstd * g1.w + e1.w);
    *reinterpret_cast<uint2*>(ohi + (size_t)row * Dv + (t + 128) * 4) = hv;
}

// ---------------------------------------------------------------------------
// Weight transpose + fp16 conversion: g_wt[z*1024 + n][k] = W_z[k][n]
// ---------------------------------------------------------------------------
__global__ void __launch_bounds__(256) wconv_kernel(const float* __restrict__ w0,
                                                    const float* __restrict__ w1,
                                                    const float* __restrict__ w2,
                                                    const float* __restrict__ w3)
{
    __shared__ float tile[32][33];
    const float* src = (blockIdx.z == 0) ? w0 : (blockIdx.z == 1) ? w1
                     : (blockIdx.z == 2) ? w2 : w3;
    int kt = blockIdx.x * 32, nt = blockIdx.y * 32;
    int tx = threadIdx.x & 31, ty = threadIdx.x >> 5;
    #pragma unroll
    for (int i = 0; i < 4; i++)
        tile[ty + 8 * i][tx] = src[(size_t)(kt + ty + 8 * i) * Dv + nt + tx];
    __syncthreads();
    size_t off = (size_t)blockIdx.z * Dv;
    #pragma unroll
    for (int i = 0; i < 4; i++) {
        int n = nt + ty + 8 * i, kk = kt + tx;
        g_wthi[(off + n) * Dv + kk] = __float2half_rn(tile[tx][ty + 8 * i]);
    }
}

// ---------------------------------------------------------------------------
// mma.sync pure-fp16 GEMM. CTA tile 128x128, 8 warps (2x4), K-chunk 32,
// 4-stage cp.async pipeline, one barrier per chunk, 2 CTAs/SM.
//   C = Ah@Bh^T     (fp32 accum)
// ---------------------------------------------------------------------------
constexpr int GTILE = 8192;                  // one 128x32 fp16 tile
constexpr int STAGE = 2 * GTILE;             // Ah|Wh (16KB)
constexpr int NSTG = 4;
constexpr int SMEM_DYN = NSTG * STAGE + 1024;

template <bool HILO>
__global__ void __launch_bounds__(256, 2) gemm_tc_kernel(
    const __half* __restrict__ Ahi,
    int wrow_off,
    float* Cf, const float* res,
    __half* Chi,
    const float* b0, const float* b1, const float* b2)
{
    extern __shared__ char dyns[];
    const uint32_t sraw = smem_to_u32(dyns);
    const uint32_t s0 = (sraw + 1023) & ~1023u;

    const int tid = threadIdx.x;
    const int bm = blockIdx.y * 128;
    const int bx = blockIdx.x;
    const int wrow = wrow_off + bx * 128;

    float acc[4][4][4];
    #pragma unroll
    for (int i = 0; i < 4; i++)
        #pragma unroll
        for (int j = 0; j < 4; j++)
            #pragma unroll
            for (int r = 0; r < 4; r++) acc[i][j][r] = 0.0f;

    // loaders: 2 tiles x 512 16B-vectors; each thread does 2 per tile
    const int lr  = tid >> 2;            // row 0..63 (then +64)
    const int lc8 = (tid & 3) * 8;       // fp16 col
    const uint32_t lcb = (tid & 3) * 16; // byte col

    auto issue_loads = [&](int c, int st) {
        const uint32_t sb = s0 + st * STAGE;
        #pragma unroll
        for (int i = 0; i < 2; i++) {
            const int r = lr + 64 * i;
            const uint32_t sw = SMEM_SWIZZLE_64B((uint32_t)(r * 64) + lcb);
            const size_t ga = (size_t)(bm + r) * Dv + c * 32 + lc8;
            const size_t gw = (size_t)(wrow + r) * Dv + c * 32 + lc8;
            CP_ASYNC16(sb + sw,         (const void*)(Ahi + ga));
            CP_ASYNC16(sb + GTILE + sw, (const void*)(g_wthi + gw));
        }
    };

    const int l = tid & 31;
    const int w = tid >> 5;
    const int wm = (w >> 2) * 64;
    const int wn = (w & 3) * 32;

    auto compute = [&](int st) {
        const uint32_t sb = s0 + st * STAGE;
        #pragma unroll
        for (int ks = 0; ks < 2; ks++) {
            uint32_t bh[4][2];
            const int bkb = ks * 32 + ((l >> 3) & 1) * 16;
            #pragma unroll
            for (int j = 0; j < 2; j++) {
                const int nr = wn + j * 16 + (l & 7) + ((l >> 4) & 1) * 8;
                const uint32_t off = SMEM_SWIZZLE_64B((uint32_t)(nr * 64 + bkb));
                uint32_t r0, r1, r2, r3;
                ldsm4(sb + GTILE + off, r0, r1, r2, r3);
                bh[2 * j][0] = r0; bh[2 * j][1] = r1;
                bh[2 * j + 1][0] = r2; bh[2 * j + 1][1] = r3;
            }
            const int akb = ks * 32 + ((l >> 4) & 1) * 16;
            #pragma unroll
            for (int mt = 0; mt < 4; mt++) {
                uint32_t ah[4];
                const int row = wm + mt * 16 + (l & 7) + ((l >> 3) & 1) * 8;
                const uint32_t off = SMEM_SWIZZLE_64B((uint32_t)(row * 64 + akb));
                ldsm4(sb + off, ah[0], ah[1], ah[2], ah[3]);
                #pragma unroll
                for (int nt = 0; nt < 4; nt++) {
                    mma16816(acc[mt][nt], ah, bh[nt]);
                }
            }
        }
    };

    issue_loads(0, 0); CP_COMMIT();
    issue_loads(1, 1); CP_COMMIT();
    issue_loads(2, 2); CP_COMMIT();
    #pragma unroll 1
    for (int c = 0; c < 32; c++) {
        if (c <= 29)      { CP_WAIT(2); }
        else if (c == 30) { CP_WAIT(1); }
        else              { CP_WAIT(0); }
        __syncthreads();
        if (c + 3 < 32) { issue_loads(c + 3, (c + 3) % NSTG); CP_COMMIT(); }
        compute(c % NSTG);
    }

    // ---- epilogue ----
    const int seg = bx >> 3;
    const float* bias = (seg == 0) ? b0 : (seg == 1) ? b1 : b2;
    // q is pre-scaled by 1/sqrt(dh) * log2(e) so softmax can use raw ex2
    const float scale = (HILO && seg == 0) ? 0.125f * 1.4426950408889634f : 1.0f;

    #pragma unroll
    for (int mt = 0; mt < 4; mt++) {
        #pragma unroll
        for (int nt = 0; nt < 4; nt++) {
            const int row = bm + wm + mt * 16 + (l >> 2);
            const int cseg = (bx & 7) * 128 + wn + nt * 8 + (l & 3) * 2;  // col within segment
            float2 bb = *reinterpret_cast<const float2*>(bias + cseg);
            float v0 = (acc[mt][nt][0] + bb.x) * scale;
            float v1 = (acc[mt][nt][1] + bb.y) * scale;
            float v2 = (acc[mt][nt][2] + bb.x) * scale;
            float v3 = (acc[mt][nt][3] + bb.y) * scale;
            if (HILO) {
                const size_t o0 = (size_t)row * 3072 + seg * 1024 + cseg;
                const size_t o1 = o0 + (size_t)8 * 3072;
                *reinterpret_cast<uint32_t*>(Chi + o0) = pack2h(v0, v1);
                *reinterpret_cast<uint32_t*>(Chi + o1) = pack2h(v2, v3);
            } else {
                const size_t g0o = (size_t)row * Dv + cseg;
                const size_t g1o = g0o + (size_t)8 * Dv;
                float2 r0 = *reinterpret_cast<const float2*>(res + g0o);
                float2 r1 = *reinterpret_cast<const float2*>(res + g1o);
                *reinterpret_cast<float2*>(Cf + g0o) = make_float2(v0 + r0.x, v1 + r0.y);
                *reinterpret_cast<float2*>(Cf + g1o) = make_float2(v2 + r1.x, v3 + r1.y);
            }
        }
    }
}

// ---------------------------------------------------------------------------
// Tensor-core flash attention, pure fp16 operands (fp32 accum/softmax):
//   S = qh.Kh ;  O += Ph.Vh
// grid (T/64, H, B), 128 threads (4 warps x 16 queries).
// Double-buffered Kh|Vh tiles (16KB/stage); one barrier per key-tile.
// ---------------------------------------------------------------------------
constexpr int AST = 16384;                   // Kh|Vh tiles (8KB each)
constexpr int ASMEM = 2 * AST + 1024;
#define MASK_PEN 144269.50f                  // 100000 * log2(e)

__global__ void __launch_bounds__(128) attn_tc_kernel(
    const __half* __restrict__ QKVhi,
    const unsigned* __restrict__ mbits,
    __half* __restrict__ Yhi)
{
    extern __shared__ char dyns[];
    const uint32_t sraw = smem_to_u32(dyns);
    const uint32_t s0a = (sraw + 1023) & ~1023u;

    const int tid = threadIdx.x, l = tid & 31, w = tid >> 5;
    const int b = blockIdx.z, h = blockIdx.y;
    const int qb = blockIdx.x * 64;
    const int rowb = b * Tv;
    const int kcol = 1024 + h * 64, vcol = 2048 + h * 64;

    // Q fragments (q pre-scaled by 0.125*log2e in QKV epilogue)
    uint32_t qh[4][4];
    const int r = l >> 2;
    const int row0 = qb + w * 16 + r;
    {
        const size_t a0 = (size_t)(rowb + row0) * 3072 + h * 64;
        const size_t a1 = a0 + (size_t)8 * 3072;
        #pragma unroll
        for (int ks = 0; ks < 4; ks++) {
            const int c0 = ks * 16 + (l & 3) * 2;
            qh[ks][0] = *reinterpret_cast<const uint32_t*>(QKVhi + a0 + c0);
            qh[ks][1] = *reinterpret_cast<const uint32_t*>(QKVhi + a1 + c0);
            qh[ks][2] = *reinterpret_cast<const uint32_t*>(QKVhi + a0 + c0 + 8);
            qh[ks][3] = *reinterpret_cast<const uint32_t*>(QKVhi + a1 + c0 + 8);
        }
    }

    float O[8][4];
    #pragma unroll
    for (int t = 0; t < 8; t++)
        #pragma unroll
        for (int i = 0; i < 4; i++) O[t][i] = 0.0f;
    float m0 = -CUDART_INF_F, m1 = -CUDART_INF_F, l0 = 0.0f, l1 = 0.0f;

    const unsigned* mr0 = mbits + (size_t)(rowb + row0) * (Tv / 32);
    const unsigned* mr1 = mr0 + (size_t)8 * (Tv / 32);

    auto issue = [&](int kt, int st) {
        const uint32_t sb = s0a + st * AST;
        #pragma unroll
        for (int i = 0; i < 4; i++) {
            const int vv = tid + 128 * i;            // 0..511
            const int rr = vv >> 3, c16 = vv & 7;
            const uint32_t sw = SMEM_SWIZZLE_128B((uint32_t)(rr * 128 + c16 * 16));
            const size_t gk = (size_t)(rowb + kt + rr) * 3072 + kcol + c16 * 8;
            const size_t gv = (size_t)(rowb + kt + rr) * 3072 + vcol + c16 * 8;
            CP_ASYNC16(sb + sw,         (const void*)(QKVhi + gk));
            CP_ASYNC16(sb + 8192 + sw,  (const void*)(QKVhi + gv));
        }
    };

    issue(0, 0); CP_COMMIT();

    #pragma unroll 1
    for (int kt = 0; kt < Tv; kt += 64) {
        const int st = (kt >> 6) & 1;
        CP_WAIT(0);
        __syncthreads();
        if (kt + 64 < Tv) { issue(kt + 64, st ^ 1); CP_COMMIT(); }

        const uint32_t kb = s0a + st * AST;
        const uint32_t vb = kb + 8192;

        // ---- S = Q K^T ----
        float S[8][4];
        #pragma unroll
        for (int t = 0; t < 8; t++)
            #pragma unroll
            for (int i = 0; i < 4; i++) S[t][i] = 0.0f;

        #pragma unroll
        for (int ks = 0; ks < 4; ks++) {
            uint32_t bh[8][2];
            #pragma unroll
            for (int j = 0; j < 4; j++) {
                const int nr = j * 16 + (l & 7) + ((l >> 4) & 1) * 8;
                const uint32_t off = SMEM_SWIZZLE_128B(
                    (uint32_t)(nr * 128 + ks * 32 + ((l >> 3) & 1) * 16));
                uint32_t r0, r1, r2, r3;
                ldsm4(kb + off, r0, r1, r2, r3);
                bh[2*j][0] = r0; bh[2*j][1] = r1; bh[2*j+1][0] = r2; bh[2*j+1][1] = r3;
            }
            #pragma unroll
            for (int t = 0; t < 8; t++) {
                mma16816(S[t], qh[ks], bh[t]);
            }
        }

        // ---- mask ----
        const int kw = kt >> 5;
        const unsigned w00 = mr0[kw], w01 = mr0[kw + 1];
        const unsigned w10 = mr1[kw], w11 = mr1[kw + 1];
        #pragma unroll
        for (int t = 0; t < 8; t++) {
            const int c = (t & 3) * 8 + (l & 3) * 2;
            const unsigned wa = (t < 4) ? w00 : w01;
            const unsigned wb = (t < 4) ? w10 : w11;
            if (!((wa >> c) & 1u))       S[t][0] -= MASK_PEN;
            if (!((wa >> (c + 1)) & 1u)) S[t][1] -= MASK_PEN;
            if (!((wb >> c) & 1u))       S[t][2] -= MASK_PEN;
            if (!((wb >> (c + 1)) & 1u)) S[t][3] -= MASK_PEN;
        }

        // ---- online softmax (log2 domain) ----
        float mx0 = -CUDART_INF_F, mx1 = -CUDART_INF_F;
        #pragma unroll
        for (int t = 0; t < 8; t++) {
            mx0 = fmaxf(mx0, fmaxf(S[t][0], S[t][1]));
            mx1 = fmaxf(mx1, fmaxf(S[t][2], S[t][3]));
        }
        mx0 = fmaxf(mx0, __shfl_xor_sync(0xffffffffu, mx0, 1));
        mx0 = fmaxf(mx0, __shfl_xor_sync(0xffffffffu, mx0, 2));
        mx1 = fmaxf(mx1, __shfl_xor_sync(0xffffffffu, mx1, 1));
        mx1 = fmaxf(mx1, __shfl_xor_sync(0xffffffffu, mx1, 2));

        const float mn0 = fmaxf(m0, mx0), mn1 = fmaxf(m1, mx1);
        const float sc0 = ex2f(m0 - mn0), sc1 = ex2f(m1 - mn1);
        m0 = mn0; m1 = mn1;
        l0 *= sc0; l1 *= sc1;

        #pragma unroll
        for (int t = 0; t < 8; t++) {
            S[t][0] = ex2f(S[t][0] - m0);
            S[t][1] = ex2f(S[t][1] - m0);
            S[t][2] = ex2f(S[t][2] - m1);
            S[t][3] = ex2f(S[t][3] - m1);
            l0 += S[t][0] + S[t][1];
            l1 += S[t][2] + S[t][3];
            O[t][0] *= sc0; O[t][1] *= sc0; O[t][2] *= sc1; O[t][3] *= sc1;
        }

        // ---- O += P V (V via ldmatrix.trans) ----
        #pragma unroll
        for (int ks = 0; ks < 4; ks++) {
            uint32_t ph[4];
            ph[0] = pack2h(S[2*ks][0],   S[2*ks][1]);
            ph[1] = pack2h(S[2*ks][2],   S[2*ks][3]);
            ph[2] = pack2h(S[2*ks+1][0], S[2*ks+1][1]);
            ph[3] = pack2h(S[2*ks+1][2], S[2*ks+1][3]);

            uint32_t vh[8][2];
            const int vr = ks * 16 + (l & 7) + ((l >> 3) & 1) * 8;
            #pragma unroll
            for (int j = 0; j < 4; j++) {
                const uint32_t off = SMEM_SWIZZLE_128B(
                    (uint32_t)(vr * 128 + (j * 16 + ((l >> 4) & 1) * 8) * 2));
                uint32_t r0, r1, r2, r3;
                ldsm4t(vb + off, r0, r1, r2, r3);
                vh[2*j][0] = r0; vh[2*j][1] = r1; vh[2*j+1][0] = r2; vh[2*j+1][1] = r3;
            }
            #pragma unroll
            for (int t = 0; t < 8; t++) {
                mma16816(O[t], ph, vh[t]);
            }
        }
    }

    // ---- finalize: normalize and emit y ----
    l0 += __shfl_xor_sync(0xffffffffu, l0, 1);
    l0 += __shfl_xor_sync(0xffffffffu, l0, 2);
    l1 += __shfl_xor_sync(0xffffffffu, l1, 1);
    l1 += __shfl_xor_sync(0xffffffffu, l1, 2);
    const float inv0 = 1.0f / l0, inv1 = 1.0f / l1;

    const size_t y0 = (size_t)(rowb + row0) * Dv + h * 64;
    const size_t y1 = y0 + (size_t)8 * Dv;
    #pragma unroll
    for (int t = 0; t < 8; t++) {
        const int col = t * 8 + (l & 3) * 2;
        *reinterpret_cast<uint32_t*>(Yhi + y0 + col) =
            pack2h(O[t][0] * inv0, O[t][1] * inv0);
        *reinterpret_cast<uint32_t*>(Yhi + y1 + col) =
            pack2h(O[t][2] * inv1, O[t][3] * inv1);
    }
}

// ---------------------------------------------------------------------------
extern "C" void kernel_launch(void* const* d_in, const int* in_sizes, int n_in,
                              void* d_out, int out_size)
{
    const float* x        = (const float*)d_in[0];
    const int*   src_mask = (const int*)  d_in[1];
    const float* ln_gamma = (const float*)d_in[2];
    const float* ln_beta  = (const float*)d_in[3];
    const float* Wq = (const float*)d_in[4];
    const float* bq = (const float*)d_in[5];
    const float* Wk = (const float*)d_in[6];
    const float* bk = (const float*)d_in[7];
    const float* Wv = (const float*)d_in[8];
    const float* bv = (const float*)d_in[9];
    const float* Wo = (const float*)d_in[10];
    const float* bo = (const float*)d_in[11];
    float* out = (float*)d_out;

    __half *xnhi, *yhi, *qkvhi;
    unsigned* mbits;
    cudaGetSymbolAddress((void**)&xnhi,  g_xnhi);
    cudaGetSymbolAddress((void**)&yhi,   g_yhi);
    cudaGetSymbolAddress((void**)&qkvhi, g_qkvhi);
    cudaGetSymbolAddress((void**)&mbits, g_mbits);

    cudaFuncSetAttribute(gemm_tc_kernel<true>,  cudaFuncAttributeMaxDynamicSharedMemorySize, SMEM_DYN);
    cudaFuncSetAttribute(gemm_tc_kernel<false>, cudaFuncAttributeMaxDynamicSharedMemorySize, SMEM_DYN);
    cudaFuncSetAttribute(attn_tc_kernel,        cudaFuncAttributeMaxDynamicSharedMemorySize, ASMEM);

    // 1. pack mask bits
    pack_mask_kernel<<<NWORDS / 8, 256>>>(src_mask, mbits);

    // 2. LayerNorm -> fp16
    ln_kernel<<<MROWS, 128>>>(x, ln_gamma, ln_beta, xnhi);

    // 3. weight transpose + fp16 conversion (Wq, Wk, Wv, Wo)
    wconv_kernel<<<dim3(Dv / 32, Dv / 32, 4), 256>>>(Wq, Wk, Wv, Wo);

    // 4. fused QKV projection -> fp16 (q pre-scaled by 0.125*log2e)
    gemm_tc_kernel<true><<<dim3(24, 32), 256, SMEM_DYN>>>(
        xnhi, 0, nullptr, nullptr, qkvhi, bq, bk, bv);

    // 5. tensor-core masked flash attention (emits y fp16)
    attn_tc_kernel<<<dim3(Tv / 64, Hv, Bv), 128, ASMEM>>>(qkvhi, mbits, yhi);

    // 6. output projection + bias + residual (fp32 out)
    gemm_tc_kernel<false><<<dim3(8, 32), 256, SMEM_DYN>>>(
        yhi, 3072, out, x, nullptr, bo, bo, bo);
}